// round 3
// baseline (speedup 1.0000x reference)
#include <cuda_runtime.h>
#include <cuda_bf16.h>
#include <math.h>

// Problem constants
#define NNODES 50000
#define E0     400000
#define ETOT   (E0 + NNODES)   // 450000 with self loops
#define HEADS  8
#define HID    64
#define HC     512             // HEADS*HID
#define F_IN   18
#define F_OUT  15
#define NEG_SLOPE 0.2f
#define EPS_DENOM 1e-16f

// ---------------- device scratch (no runtime allocs allowed) ----------------
__device__ float g_h[(size_t)NNODES * HC];     // h = x @ W (per layer)
__device__ float g_out[(size_t)NNODES * HC];   // aggregated output per layer
__device__ float g_xin[(size_t)NNODES * HC];   // layer input features (x1, x2)
__device__ float g_alpha_s[NNODES * HEADS];
__device__ float g_alpha_d[NNODES * HEADS];
__device__ float g_m[NNODES * HEADS];
__device__ float g_denom[NNODES * HEADS];
__device__ float g_ex[(size_t)ETOT * HEADS];
__device__ int   g_src[ETOT];
__device__ int   g_dst[ETOT];
__device__ int   g_is64;

// ---------------- helpers ----------------
__device__ __forceinline__ void atomicMaxFloat(float* addr, float value) {
    // works for mixed signs given init = -inf
    if (value >= 0.0f) {
        atomicMax((int*)addr, __float_as_int(value));
    } else {
        atomicMin((unsigned int*)addr, __float_as_uint(value));
    }
}

// ---------------- kernels ----------------

// Detect whether edge_index is int64 or int32. Node ids < 50000 (< 2^31), so
// for little-endian int64 data every odd 32-bit word of the stream is 0.
// For random int32 node ids the chance a word is 0 is ~1e-5 per word.
__global__ void detect_dtype_kernel(const int* __restrict__ w) {
    if (threadIdx.x == 0 && blockIdx.x == 0) {
        int is64 = 1;
        #pragma unroll 1
        for (int i = 1; i < 2048; i += 2) {
            if (w[i] != 0) { is64 = 0; break; }
        }
        g_is64 = is64;
    }
}

// Convert edge_index (int32 or int64) -> int32 src/dst and append self loops.
__global__ void edge_conv_kernel(const void* __restrict__ eiv) {
    int i = blockIdx.x * blockDim.x + threadIdx.x;
    bool is64 = (g_is64 != 0);
    if (i < E0) {
        int s, d;
        if (is64) {
            const long long* e = (const long long*)eiv;
            s = (int)e[i];
            d = (int)e[E0 + i];
        } else {
            const int* e = (const int*)eiv;
            s = e[i];
            d = e[E0 + i];
        }
        g_src[i] = s;
        g_dst[i] = d;
    } else if (i < ETOT) {
        int n = i - E0;
        g_src[i] = n;
        g_dst[i] = n;
    }
}

// Generic fp32 tiled GEMM: C[M,Ncol] = A[M,K] @ B[K,Ncol]
#define BM 64
#define BN 64
#define BK 16
__global__ void gemm_kernel(const float* __restrict__ A, const float* __restrict__ B,
                            float* __restrict__ C, int M, int K, int Ncol) {
    __shared__ float As[BK][BM + 1];
    __shared__ float Bs[BK][BN + 1];
    int bm = blockIdx.y * BM;
    int bn = blockIdx.x * BN;
    int tid = threadIdx.x;                 // 256 threads
    int tr = (tid >> 4) * 4;               // 0..60
    int tc = (tid & 15) * 4;               // 0..60

    float acc[4][4] = {};
    for (int k0 = 0; k0 < K; k0 += BK) {
        // load A tile (BM x BK), transposed into As[k][m]
        #pragma unroll
        for (int i = tid; i < BM * BK; i += 256) {
            int m = i / BK, k = i % BK;
            int gm = bm + m, gk = k0 + k;
            As[k][m] = (gm < M && gk < K) ? A[(size_t)gm * K + gk] : 0.0f;
        }
        // load B tile (BK x BN)
        #pragma unroll
        for (int i = tid; i < BK * BN; i += 256) {
            int k = i / BN, n = i % BN;
            int gk = k0 + k, gn = bn + n;
            Bs[k][n] = (gk < K && gn < Ncol) ? B[(size_t)gk * Ncol + gn] : 0.0f;
        }
        __syncthreads();
        #pragma unroll
        for (int k = 0; k < BK; k++) {
            float a[4], b[4];
            #pragma unroll
            for (int i = 0; i < 4; i++) a[i] = As[k][tr + i];
            #pragma unroll
            for (int j = 0; j < 4; j++) b[j] = Bs[k][tc + j];
            #pragma unroll
            for (int i = 0; i < 4; i++)
                #pragma unroll
                for (int j = 0; j < 4; j++) acc[i][j] += a[i] * b[j];
        }
        __syncthreads();
    }
    #pragma unroll
    for (int i = 0; i < 4; i++) {
        int gm = bm + tr + i;
        if (gm >= M) continue;
        #pragma unroll
        for (int j = 0; j < 4; j++) {
            int gn = bn + tc + j;
            if (gn < Ncol) C[(size_t)gm * Ncol + gn] = acc[i][j];
        }
    }
}

// Per-node: alpha_s/alpha_d dot products, init m/denom, zero out-buffer.
// grid = NNODES blocks, 256 threads (8 warps -> 8 heads)
__global__ void alpha_init_kernel(const float* __restrict__ a_src,
                                  const float* __restrict__ a_dst) {
    int n = blockIdx.x;
    int tid = threadIdx.x;
    int w = tid >> 5, lane = tid & 31;

    // zero aggregation buffer rows
    g_out[(size_t)n * HC + tid] = 0.0f;
    g_out[(size_t)n * HC + 256 + tid] = 0.0f;

    const float* hp = g_h + (size_t)n * HC + w * HID;
    float h0 = hp[lane], h1 = hp[lane + 32];
    const float* as = a_src + w * HID;
    const float* ad = a_dst + w * HID;
    float s = h0 * as[lane] + h1 * as[lane + 32];
    float d = h0 * ad[lane] + h1 * ad[lane + 32];
    #pragma unroll
    for (int off = 16; off > 0; off >>= 1) {
        s += __shfl_down_sync(0xFFFFFFFFu, s, off);
        d += __shfl_down_sync(0xFFFFFFFFu, d, off);
    }
    if (lane == 0) {
        g_alpha_s[n * HEADS + w] = s;
        g_alpha_d[n * HEADS + w] = d;
        g_m[n * HEADS + w] = -INFINITY;
        g_denom[n * HEADS + w] = 0.0f;
    }
}

// Pass A: segment max of leaky-relu'd logits
__global__ void edge_max_kernel() {
    int e = blockIdx.x * blockDim.x + threadIdx.x;
    if (e >= ETOT) return;
    int s = g_src[e], d = g_dst[e];
    const float4* asv = (const float4*)(g_alpha_s + s * HEADS);
    const float4* adv = (const float4*)(g_alpha_d + d * HEADS);
    float4 s0 = asv[0], s1 = asv[1];
    float4 d0 = adv[0], d1 = adv[1];
    float ev[8] = { s0.x + d0.x, s0.y + d0.y, s0.z + d0.z, s0.w + d0.w,
                    s1.x + d1.x, s1.y + d1.y, s1.z + d1.z, s1.w + d1.w };
    #pragma unroll
    for (int h = 0; h < 8; h++) {
        float v = ev[h];
        v = v > 0.0f ? v : NEG_SLOPE * v;
        atomicMaxFloat(&g_m[d * HEADS + h], v);
    }
}

// Pass B: exp(e - m[dst]), store, accumulate denom
__global__ void edge_exp_kernel() {
    int e = blockIdx.x * blockDim.x + threadIdx.x;
    if (e >= ETOT) return;
    int s = g_src[e], d = g_dst[e];
    const float4* asv = (const float4*)(g_alpha_s + s * HEADS);
    const float4* adv = (const float4*)(g_alpha_d + d * HEADS);
    const float4* mv  = (const float4*)(g_m + d * HEADS);
    float4 s0 = asv[0], s1 = asv[1];
    float4 d0 = adv[0], d1 = adv[1];
    float4 m0 = mv[0],  m1 = mv[1];
    float ev[8] = { s0.x + d0.x, s0.y + d0.y, s0.z + d0.z, s0.w + d0.w,
                    s1.x + d1.x, s1.y + d1.y, s1.z + d1.z, s1.w + d1.w };
    float mm[8] = { m0.x, m0.y, m0.z, m0.w, m1.x, m1.y, m1.z, m1.w };
    #pragma unroll
    for (int h = 0; h < 8; h++) {
        float v = ev[h];
        v = v > 0.0f ? v : NEG_SLOPE * v;
        float ex = expf(v - mm[h]);
        g_ex[(size_t)e * HEADS + h] = ex;
        atomicAdd(&g_denom[d * HEADS + h], ex);
    }
}

// Pass C: warp per edge, out[dst] += h[src] * alpha
__global__ void edge_aggr_kernel() {
    int gw = (blockIdx.x * blockDim.x + threadIdx.x) >> 5;
    int lane = threadIdx.x & 31;
    if (gw >= ETOT) return;
    int s = g_src[gw], d = g_dst[gw];
    float av = 0.0f;
    if (lane < 8) av = g_ex[(size_t)gw * HEADS + lane] / (g_denom[d * HEADS + lane] + EPS_DENOM);
    const float* hp = g_h + (size_t)s * HC;
    float* op = g_out + (size_t)d * HC;
    #pragma unroll
    for (int it = 0; it < 16; it++) {
        float a = __shfl_sync(0xFFFFFFFFu, av, it >> 1);
        int idx = it * 32 + lane;
        atomicAdd(&op[idx], hp[idx] * a);
    }
}

// Layers 1,2: x_next = elu(out + bias)
__global__ void post_elu_kernel(const float* __restrict__ bias) {
    size_t idx = (size_t)blockIdx.x * blockDim.x + threadIdx.x;
    size_t total = (size_t)NNODES * HC;
    if (idx >= total) return;
    float v = g_out[idx] + bias[idx & (HC - 1)];
    g_xin[idx] = v > 0.0f ? v : expm1f(v);
}

// Layer 3: mean over heads + b3, then @ W_out + b_out. 64 threads per node.
__global__ void final_kernel(const float* __restrict__ b3,
                             const float* __restrict__ W_out,
                             const float* __restrict__ b_out,
                             float* __restrict__ y) {
    __shared__ float x3[HID];
    __shared__ float Wl[HID * F_OUT];
    int n = blockIdx.x;
    int tid = threadIdx.x;  // 64
    for (int i = tid; i < HID * F_OUT; i += HID) Wl[i] = W_out[i];
    const float* p = g_out + (size_t)n * HC + tid;
    float acc = 0.0f;
    #pragma unroll
    for (int h = 0; h < HEADS; h++) acc += p[h * HID];
    x3[tid] = acc * (1.0f / HEADS) + b3[tid];
    __syncthreads();
    if (tid < F_OUT) {
        float s = b_out[tid];
        #pragma unroll
        for (int c = 0; c < HID; c++) s += x3[c] * Wl[c * F_OUT + tid];
        y[(size_t)n * F_OUT + tid] = s;
    }
}

// ---------------- launcher ----------------
extern "C" void kernel_launch(void* const* d_in, const int* in_sizes, int n_in,
                              void* d_out, int out_size) {
    const float* x      = (const float*)d_in[0];
    const void*  ei     = d_in[1];
    const float* W1     = (const float*)d_in[2];
    const float* a1_src = (const float*)d_in[3];
    const float* a1_dst = (const float*)d_in[4];
    const float* b1     = (const float*)d_in[5];
    const float* W2     = (const float*)d_in[6];
    const float* a2_src = (const float*)d_in[7];
    const float* a2_dst = (const float*)d_in[8];
    const float* b2     = (const float*)d_in[9];
    const float* W3     = (const float*)d_in[10];
    const float* a3_src = (const float*)d_in[11];
    const float* a3_dst = (const float*)d_in[12];
    const float* b3     = (const float*)d_in[13];
    const float* W_out  = (const float*)d_in[14];
    const float* b_out  = (const float*)d_in[15];
    float*       y      = (float*)d_out;

    float *p_h, *p_xin;
    cudaGetSymbolAddress((void**)&p_h, g_h);
    cudaGetSymbolAddress((void**)&p_xin, g_xin);

    // edge conversion + self loops (dtype-sniffing: int32 vs int64)
    detect_dtype_kernel<<<1, 32>>>((const int*)ei);
    edge_conv_kernel<<<(ETOT + 255) / 256, 256>>>(ei);

    const int edge_blocks = (ETOT + 255) / 256;
    const int aggr_blocks = (ETOT * 32 + 255) / 256;  // warp per edge
    const size_t total_nh = (size_t)NNODES * HC;
    const int elu_blocks = (int)((total_nh + 255) / 256);
    dim3 gemm_grid(HC / BN, (NNODES + BM - 1) / BM);

    // ---- layer 1 ----
    gemm_kernel<<<gemm_grid, 256>>>(x, W1, p_h, NNODES, F_IN, HC);
    alpha_init_kernel<<<NNODES, 256>>>(a1_src, a1_dst);
    edge_max_kernel<<<edge_blocks, 256>>>();
    edge_exp_kernel<<<edge_blocks, 256>>>();
    edge_aggr_kernel<<<aggr_blocks, 256>>>();
    post_elu_kernel<<<elu_blocks, 256>>>(b1);

    // ---- layer 2 ----
    gemm_kernel<<<gemm_grid, 256>>>(p_xin, W2, p_h, NNODES, HC, HC);
    alpha_init_kernel<<<NNODES, 256>>>(a2_src, a2_dst);
    edge_max_kernel<<<edge_blocks, 256>>>();
    edge_exp_kernel<<<edge_blocks, 256>>>();
    edge_aggr_kernel<<<aggr_blocks, 256>>>();
    post_elu_kernel<<<elu_blocks, 256>>>(b2);

    // ---- layer 3 ----
    gemm_kernel<<<gemm_grid, 256>>>(p_xin, W3, p_h, NNODES, HC, HC);
    alpha_init_kernel<<<NNODES, 256>>>(a3_src, a3_dst);
    edge_max_kernel<<<edge_blocks, 256>>>();
    edge_exp_kernel<<<edge_blocks, 256>>>();
    edge_aggr_kernel<<<aggr_blocks, 256>>>();
    final_kernel<<<NNODES, HID>>>(b3, W_out, b_out, y);
}

// round 12
// speedup vs baseline: 2.1837x; 2.1837x over previous
#include <cuda_runtime.h>
#include <cuda_bf16.h>
#include <math.h>
#include <cstdint>

// Problem constants
#define NNODES 50000
#define E0     400000
#define ETOT   (E0 + NNODES)   // 450000 with self loops
#define HEADS  8
#define HID    64
#define HC     512             // HEADS*HID
#define F_IN   18
#define F_OUT  15
#define NEG_SLOPE 0.2f
#define EPS_DENOM 1e-16f
#define KP_BIG 1536            // 3*512 augmented-K for bf16 split
#define KP_SMALL 64            // 3*18=54 padded to 64

// ---------------- device scratch (no runtime allocs allowed) ----------------
__device__ float g_h[(size_t)NNODES * HC];     // h = x @ W (per layer)
__device__ float g_out[(size_t)NNODES * HC];   // aggregated output per layer
__device__ float g_xin[(size_t)NNODES * HC];   // layer input features (x1, x2)
__device__ float g_alpha_s[NNODES * HEADS];
__device__ float g_alpha_d[NNODES * HEADS];
__device__ float g_m[NNODES * HEADS];
__device__ float g_denom[NNODES * HEADS];
__device__ float g_ex[(size_t)ETOT * HEADS];
__device__ int   g_src[ETOT];
__device__ int   g_dst[ETOT];
__device__ int   g_is64;
__device__ __nv_bfloat16 g_abf[(size_t)NNODES * KP_BIG];  // A' = [Ah|Al|Ah]
__device__ __nv_bfloat16 g_bt[(size_t)HC * KP_BIG];       // B'^T = per out-col [Bh|Bh|Bl]

// ---------------- helpers ----------------
__device__ __forceinline__ uint32_t smem_to_u32(const void* p) {
    uint32_t a;
    asm("{ .reg .u64 t; cvta.to.shared.u64 t, %1; cvt.u32.u64 %0, t; }" : "=r"(a) : "l"(p));
    return a;
}
__device__ __forceinline__ void atomicMaxFloat(float* addr, float value) {
    if (value >= 0.0f) atomicMax((int*)addr, __float_as_int(value));
    else               atomicMin((unsigned int*)addr, __float_as_uint(value));
}

// ---------------- edge index ----------------
__global__ void detect_dtype_kernel(const int* __restrict__ w) {
    if (threadIdx.x == 0 && blockIdx.x == 0) {
        int is64 = 1;
        #pragma unroll 1
        for (int i = 1; i < 2048; i += 2) if (w[i] != 0) { is64 = 0; break; }
        g_is64 = is64;
    }
}
__global__ void edge_conv_kernel(const void* __restrict__ eiv) {
    int i = blockIdx.x * blockDim.x + threadIdx.x;
    bool is64 = (g_is64 != 0);
    if (i < E0) {
        int s, d;
        if (is64) {
            const long long* e = (const long long*)eiv;
            s = (int)e[i]; d = (int)e[E0 + i];
        } else {
            const int* e = (const int*)eiv;
            s = e[i]; d = e[E0 + i];
        }
        g_src[i] = s; g_dst[i] = d;
    } else if (i < ETOT) {
        int n = i - E0;
        g_src[i] = n; g_dst[i] = n;
    }
}

// ---------------- bf16 split prep ----------------
__global__ void split_a_kernel(const float* __restrict__ X, int K, int Kp) {
    size_t t = (size_t)blockIdx.x * blockDim.x + threadIdx.x;
    size_t total = (size_t)NNODES * K;
    if (t >= total) return;
    int m = (int)(t / K), k = (int)(t % K);
    float v = X[t];
    __nv_bfloat16 hi = __float2bfloat16(v);
    __nv_bfloat16 lo = __float2bfloat16(v - __bfloat162float(hi));
    __nv_bfloat16* row = g_abf + (size_t)m * Kp;
    row[k] = hi; row[K + k] = lo; row[2 * K + k] = hi;
}
__global__ void split_a_small_kernel(const float* __restrict__ X, int K, int Kp) {
    size_t t = (size_t)blockIdx.x * blockDim.x + threadIdx.x;
    size_t total = (size_t)NNODES * Kp;
    if (t >= total) return;
    int m = (int)(t / Kp), c = (int)(t % Kp);
    __nv_bfloat16 o = __float2bfloat16(0.0f);
    if (c < K) {
        o = __float2bfloat16(X[(size_t)m * K + c]);
    } else if (c < 2 * K) {
        float v = X[(size_t)m * K + (c - K)];
        __nv_bfloat16 hi = __float2bfloat16(v);
        o = __float2bfloat16(v - __bfloat162float(hi));
    } else if (c < 3 * K) {
        o = __float2bfloat16(X[(size_t)m * K + (c - 2 * K)]);
    }
    g_abf[t] = o;
}
__global__ void split_b_kernel(const float* __restrict__ W, int K, int Kp) {
    int t = blockIdx.x * blockDim.x + threadIdx.x;
    int total = HC * Kp;
    if (t >= total) return;
    int n = t / Kp, c = t % Kp;
    __nv_bfloat16 o = __float2bfloat16(0.0f);
    if (c < 2 * K) {
        int k = (c < K) ? c : (c - K);
        o = __float2bfloat16(W[(size_t)k * HC + n]);
    } else if (c < 3 * K) {
        float v = W[(size_t)(c - 2 * K) * HC + n];
        __nv_bfloat16 hi = __float2bfloat16(v);
        o = __float2bfloat16(v - __bfloat162float(hi));
    }
    g_bt[t] = o;
}

// ---------------- mma.sync bf16 GEMM: C[M,512] = A'[M,Kp] x (Bt[512,Kp])^T ----------------
// CTA: 256 thr (8 warps as 2x4), tile 128x128, BK=32, 3-stage cp.async pipeline.
// smem stage: A 128 rows x 40 bf16 (80B padded stride), B same. 20480 B/stage.
#define STAGES 3
#define GBK 32
#define ROWB 80           // padded row stride in bytes (40 bf16) -> zero-conflict frag loads
#define STAGE_A 10240
#define STAGE_BYTES 20480
#define GSMEM (STAGES * STAGE_BYTES)   // 61440

__device__ __forceinline__ void cp_async16(uint32_t dst, const void* src, int src_size) {
    asm volatile("cp.async.cg.shared.global [%0], [%1], 16, %2;"
                 :: "r"(dst), "l"(src), "r"(src_size) : "memory");
}

__global__ void __launch_bounds__(256) mma_gemm_kernel(
    const __nv_bfloat16* __restrict__ A,
    const __nv_bfloat16* __restrict__ Bt,
    float* __restrict__ C, int M, int Kp)
{
    extern __shared__ char smem[];
    uint32_t sb = smem_to_u32(smem);
    int tid = threadIdx.x, wid = tid >> 5, lane = tid & 31;
    int m0 = blockIdx.y * 128, n0 = blockIdx.x * 128;
    int wm = (wid >> 2) * 64, wn = (wid & 3) * 32;
    int g = lane >> 2, q = lane & 3;

    float acc[4][4][4];
    #pragma unroll
    for (int a = 0; a < 4; a++)
        #pragma unroll
        for (int b = 0; b < 4; b++)
            #pragma unroll
            for (int c = 0; c < 4; c++) acc[a][b][c] = 0.0f;

    const int T = Kp / GBK;

    // issue cp.async group for k-tile t into stage s
    auto issue = [&](int t, int s) {
        uint32_t sa = sb + s * STAGE_BYTES;
        uint32_t sB = sa + STAGE_A;
        int k0 = t * GBK;
        #pragma unroll
        for (int i = 0; i < 2; i++) {
            int idx = i * 256 + tid;
            int r = idx >> 2, c = idx & 3;
            // A tile (M-guarded via zero-fill)
            int sz = (m0 + r) < M ? 16 : 0;
            cp_async16(sa + r * ROWB + c * 16, A + (size_t)(m0 + r) * Kp + k0 + c * 8, sz);
            // B tile (always in range: 512 % 128 == 0)
            cp_async16(sB + r * ROWB + c * 16, Bt + (size_t)(n0 + r) * Kp + k0 + c * 8, 16);
        }
        asm volatile("cp.async.commit_group;" ::: "memory");
    };

    int pre = (STAGES - 1 < T) ? STAGES - 1 : T;
    for (int s = 0; s < pre; s++) issue(s, s);

    for (int t = 0; t < T; t++) {
        asm volatile("cp.async.wait_group %0;" :: "n"(STAGES - 2));
        __syncthreads();
        // Maintain the commit-count invariant: commit EVERY iteration, empty at the tail.
        // (Before computing tile t: committed == t + STAGES - 1; wait_group(STAGES-2)
        //  then guarantees groups <= t are complete.)
        if (t + STAGES - 1 < T) {
            issue(t + STAGES - 1, (t + STAGES - 1) % STAGES);
        } else {
            asm volatile("cp.async.commit_group;" ::: "memory");
        }

        uint32_t sa = sb + (t % STAGES) * STAGE_BYTES;
        uint32_t sB = sa + STAGE_A;
        #pragma unroll
        for (int ks = 0; ks < 2; ks++) {
            int kb = ks * 16;
            uint32_t ar[4][4], br[4][2];
            #pragma unroll
            for (int mi = 0; mi < 4; mi++) {
                uint32_t base = sa + (wm + mi * 16 + g) * ROWB + (kb + q * 2) * 2;
                asm volatile("ld.shared.b32 %0, [%1];" : "=r"(ar[mi][0]) : "r"(base));
                asm volatile("ld.shared.b32 %0, [%1];" : "=r"(ar[mi][1]) : "r"(base + 8 * ROWB));
                asm volatile("ld.shared.b32 %0, [%1];" : "=r"(ar[mi][2]) : "r"(base + 16));
                asm volatile("ld.shared.b32 %0, [%1];" : "=r"(ar[mi][3]) : "r"(base + 8 * ROWB + 16));
            }
            #pragma unroll
            for (int ni = 0; ni < 4; ni++) {
                uint32_t base = sB + (wn + ni * 8 + g) * ROWB + (kb + q * 2) * 2;
                asm volatile("ld.shared.b32 %0, [%1];" : "=r"(br[ni][0]) : "r"(base));
                asm volatile("ld.shared.b32 %0, [%1];" : "=r"(br[ni][1]) : "r"(base + 16));
            }
            #pragma unroll
            for (int mi = 0; mi < 4; mi++)
                #pragma unroll
                for (int ni = 0; ni < 4; ni++) {
                    asm volatile(
                        "mma.sync.aligned.m16n8k16.row.col.f32.bf16.bf16.f32 "
                        "{%0,%1,%2,%3}, {%4,%5,%6,%7}, {%8,%9}, {%0,%1,%2,%3};"
                        : "+f"(acc[mi][ni][0]), "+f"(acc[mi][ni][1]),
                          "+f"(acc[mi][ni][2]), "+f"(acc[mi][ni][3])
                        : "r"(ar[mi][0]), "r"(ar[mi][1]), "r"(ar[mi][2]), "r"(ar[mi][3]),
                          "r"(br[ni][0]), "r"(br[ni][1]));
                }
        }
    }

    // epilogue: direct float2 stores
    #pragma unroll
    for (int mi = 0; mi < 4; mi++) {
        int row = m0 + wm + mi * 16 + g;
        #pragma unroll
        for (int ni = 0; ni < 4; ni++) {
            int col = n0 + wn + ni * 8 + q * 2;
            if (row < M)
                *(float2*)&C[(size_t)row * HC + col] = make_float2(acc[mi][ni][0], acc[mi][ni][1]);
            if (row + 8 < M)
                *(float2*)&C[(size_t)(row + 8) * HC + col] = make_float2(acc[mi][ni][2], acc[mi][ni][3]);
        }
    }
}

// ---------------- attention / aggregation pipeline ----------------
__global__ void alpha_init_kernel(const float* __restrict__ a_src,
                                  const float* __restrict__ a_dst) {
    int n = blockIdx.x;
    int tid = threadIdx.x;
    int w = tid >> 5, lane = tid & 31;
    g_out[(size_t)n * HC + tid] = 0.0f;
    g_out[(size_t)n * HC + 256 + tid] = 0.0f;
    const float* hp = g_h + (size_t)n * HC + w * HID;
    float h0 = hp[lane], h1 = hp[lane + 32];
    const float* as = a_src + w * HID;
    const float* ad = a_dst + w * HID;
    float s = h0 * as[lane] + h1 * as[lane + 32];
    float d = h0 * ad[lane] + h1 * ad[lane + 32];
    #pragma unroll
    for (int off = 16; off > 0; off >>= 1) {
        s += __shfl_down_sync(0xFFFFFFFFu, s, off);
        d += __shfl_down_sync(0xFFFFFFFFu, d, off);
    }
    if (lane == 0) {
        g_alpha_s[n * HEADS + w] = s;
        g_alpha_d[n * HEADS + w] = d;
        g_m[n * HEADS + w] = -INFINITY;
        g_denom[n * HEADS + w] = 0.0f;
    }
}

__global__ void edge_max_kernel() {
    int e = blockIdx.x * blockDim.x + threadIdx.x;
    if (e >= ETOT) return;
    int s = g_src[e], d = g_dst[e];
    const float4* asv = (const float4*)(g_alpha_s + s * HEADS);
    const float4* adv = (const float4*)(g_alpha_d + d * HEADS);
    float4 s0 = asv[0], s1 = asv[1];
    float4 d0 = adv[0], d1 = adv[1];
    float ev[8] = { s0.x + d0.x, s0.y + d0.y, s0.z + d0.z, s0.w + d0.w,
                    s1.x + d1.x, s1.y + d1.y, s1.z + d1.z, s1.w + d1.w };
    #pragma unroll
    for (int h = 0; h < 8; h++) {
        float v = ev[h];
        v = v > 0.0f ? v : NEG_SLOPE * v;
        atomicMaxFloat(&g_m[d * HEADS + h], v);
    }
}

__global__ void edge_exp_kernel() {
    int e = blockIdx.x * blockDim.x + threadIdx.x;
    if (e >= ETOT) return;
    int s = g_src[e], d = g_dst[e];
    const float4* asv = (const float4*)(g_alpha_s + s * HEADS);
    const float4* adv = (const float4*)(g_alpha_d + d * HEADS);
    const float4* mv  = (const float4*)(g_m + d * HEADS);
    float4 s0 = asv[0], s1 = asv[1];
    float4 d0 = adv[0], d1 = adv[1];
    float4 m0 = mv[0],  m1 = mv[1];
    float ev[8] = { s0.x + d0.x, s0.y + d0.y, s0.z + d0.z, s0.w + d0.w,
                    s1.x + d1.x, s1.y + d1.y, s1.z + d1.z, s1.w + d1.w };
    float mm[8] = { m0.x, m0.y, m0.z, m0.w, m1.x, m1.y, m1.z, m1.w };
    #pragma unroll
    for (int h = 0; h < 8; h++) {
        float v = ev[h];
        v = v > 0.0f ? v : NEG_SLOPE * v;
        float ex = expf(v - mm[h]);
        g_ex[(size_t)e * HEADS + h] = ex;
        atomicAdd(&g_denom[d * HEADS + h], ex);
    }
}

// Warp per edge; vectorized reductions: 4x red.global.add.v4.f32 per lane.
// Element index it*128 + 4*lane -> head = 2*it + (lane>>4); all 4 elems same head.
__global__ void edge_aggr_kernel() {
    int gw = (blockIdx.x * blockDim.x + threadIdx.x) >> 5;
    int lane = threadIdx.x & 31;
    if (gw >= ETOT) return;
    int s = g_src[gw], d = g_dst[gw];
    float av = 0.0f;
    if (lane < 8) av = g_ex[(size_t)gw * HEADS + lane] / (g_denom[d * HEADS + lane] + EPS_DENOM);
    const float4* hp = (const float4*)(g_h + (size_t)s * HC);
    float* op = g_out + (size_t)d * HC;
    #pragma unroll
    for (int it = 0; it < 4; it++) {
        int h = it * 2 + (lane >> 4);
        float a = __shfl_sync(0xFFFFFFFFu, av, h);
        int vidx = it * 32 + lane;
        float4 hv = hp[vidx];
        float* addr = op + vidx * 4;
        asm volatile("red.global.add.v4.f32 [%0], {%1, %2, %3, %4};"
                     :: "l"(addr), "f"(hv.x * a), "f"(hv.y * a), "f"(hv.z * a), "f"(hv.w * a)
                     : "memory");
    }
}

__global__ void post_elu_kernel(const float* __restrict__ bias) {
    size_t idx = (size_t)blockIdx.x * blockDim.x + threadIdx.x;
    size_t total = (size_t)NNODES * HC;
    if (idx >= total) return;
    float v = g_out[idx] + bias[idx & (HC - 1)];
    g_xin[idx] = v > 0.0f ? v : expm1f(v);
}

__global__ void final_kernel(const float* __restrict__ b3,
                             const float* __restrict__ W_out,
                             const float* __restrict__ b_out,
                             float* __restrict__ y) {
    __shared__ float x3[HID];
    __shared__ float Wl[HID * F_OUT];
    int n = blockIdx.x;
    int tid = threadIdx.x;  // 64
    for (int i = tid; i < HID * F_OUT; i += HID) Wl[i] = W_out[i];
    const float* p = g_out + (size_t)n * HC + tid;
    float acc = 0.0f;
    #pragma unroll
    for (int h = 0; h < HEADS; h++) acc += p[h * HID];
    x3[tid] = acc * (1.0f / HEADS) + b3[tid];
    __syncthreads();
    if (tid < F_OUT) {
        float s = b_out[tid];
        #pragma unroll
        for (int c = 0; c < HID; c++) s += x3[c] * Wl[c * F_OUT + tid];
        y[(size_t)n * F_OUT + tid] = s;
    }
}

// ---------------- launcher ----------------
extern "C" void kernel_launch(void* const* d_in, const int* in_sizes, int n_in,
                              void* d_out, int out_size) {
    const float* x      = (const float*)d_in[0];
    const void*  ei     = d_in[1];
    const float* W1     = (const float*)d_in[2];
    const float* a1_src = (const float*)d_in[3];
    const float* a1_dst = (const float*)d_in[4];
    const float* b1     = (const float*)d_in[5];
    const float* W2     = (const float*)d_in[6];
    const float* a2_src = (const float*)d_in[7];
    const float* a2_dst = (const float*)d_in[8];
    const float* b2     = (const float*)d_in[9];
    const float* W3     = (const float*)d_in[10];
    const float* a3_src = (const float*)d_in[11];
    const float* a3_dst = (const float*)d_in[12];
    const float* b3     = (const float*)d_in[13];
    const float* W_out  = (const float*)d_in[14];
    const float* b_out  = (const float*)d_in[15];
    float*       y      = (float*)d_out;

    float *p_h, *p_xin;
    __nv_bfloat16 *p_abf, *p_bt;
    cudaGetSymbolAddress((void**)&p_h, g_h);
    cudaGetSymbolAddress((void**)&p_xin, g_xin);
    cudaGetSymbolAddress((void**)&p_abf, g_abf);
    cudaGetSymbolAddress((void**)&p_bt, g_bt);

    cudaFuncSetAttribute(mma_gemm_kernel, cudaFuncAttributeMaxDynamicSharedMemorySize, GSMEM);

    detect_dtype_kernel<<<1, 32>>>((const int*)ei);
    edge_conv_kernel<<<(ETOT + 255) / 256, 256>>>(ei);

    const int edge_blocks = (ETOT + 255) / 256;
    const int aggr_blocks = (ETOT * 32 + 255) / 256;
    const size_t total_nh = (size_t)NNODES * HC;
    const int elu_blocks = (int)((total_nh + 255) / 256);
    dim3 ggrid(HC / 128, (NNODES + 127) / 128);  // (4, 391)

    // ---- layer 1 (K=18, Kp=64) ----
    {
        size_t na = (size_t)NNODES * KP_SMALL;
        split_a_small_kernel<<<(int)((na + 255) / 256), 256>>>(x, F_IN, KP_SMALL);
        split_b_kernel<<<(HC * KP_SMALL + 255) / 256, 256>>>(W1, F_IN, KP_SMALL);
        mma_gemm_kernel<<<ggrid, 256, GSMEM>>>(p_abf, p_bt, p_h, NNODES, KP_SMALL);
    }
    alpha_init_kernel<<<NNODES, 256>>>(a1_src, a1_dst);
    edge_max_kernel<<<edge_blocks, 256>>>();
    edge_exp_kernel<<<edge_blocks, 256>>>();
    edge_aggr_kernel<<<aggr_blocks, 256>>>();
    post_elu_kernel<<<elu_blocks, 256>>>(b1);

    // ---- layer 2 (K=512, Kp=1536) ----
    {
        size_t na = (size_t)NNODES * HC;
        split_a_kernel<<<(int)((na + 255) / 256), 256>>>(p_xin, HC, KP_BIG);
        split_b_kernel<<<(HC * KP_BIG + 255) / 256, 256>>>(W2, HC, KP_BIG);
        mma_gemm_kernel<<<ggrid, 256, GSMEM>>>(p_abf, p_bt, p_h, NNODES, KP_BIG);
    }
    alpha_init_kernel<<<NNODES, 256>>>(a2_src, a2_dst);
    edge_max_kernel<<<edge_blocks, 256>>>();
    edge_exp_kernel<<<edge_blocks, 256>>>();
    edge_aggr_kernel<<<aggr_blocks, 256>>>();
    post_elu_kernel<<<elu_blocks, 256>>>(b2);

    // ---- layer 3 (K=512, Kp=1536) ----
    {
        size_t na = (size_t)NNODES * HC;
        split_a_kernel<<<(int)((na + 255) / 256), 256>>>(p_xin, HC, KP_BIG);
        split_b_kernel<<<(HC * KP_BIG + 255) / 256, 256>>>(W3, HC, KP_BIG);
        mma_gemm_kernel<<<ggrid, 256, GSMEM>>>(p_abf, p_bt, p_h, NNODES, KP_BIG);
    }
    alpha_init_kernel<<<NNODES, 256>>>(a3_src, a3_dst);
    edge_max_kernel<<<edge_blocks, 256>>>();
    edge_exp_kernel<<<edge_blocks, 256>>>();
    edge_aggr_kernel<<<aggr_blocks, 256>>>();
    final_kernel<<<NNODES, HID>>>(b3, W_out, b_out, y);
}

// round 13
// speedup vs baseline: 2.4820x; 1.1366x over previous
#include <cuda_runtime.h>
#include <cuda_bf16.h>
#include <math.h>
#include <cstdint>

// Problem constants
#define NNODES 50000
#define E0     400000
#define ETOT   (E0 + NNODES)   // 450000 with self loops
#define HEADS  8
#define HID    64
#define HC     512             // HEADS*HID
#define F_IN   18
#define F_OUT  15
#define NEG_SLOPE 0.2f
#define EPS_DENOM 1e-16f
#define KP_BIG 1536            // 3*512 augmented-K for bf16 split
#define KP_SMALL 64            // 3*18=54 padded to 64

// ---------------- device scratch (no runtime allocs allowed) ----------------
__device__ float g_h[(size_t)NNODES * HC];     // h = x @ W (per layer)
__device__ float g_out[(size_t)NNODES * HC];   // aggregated output per layer
__device__ float g_xin[(size_t)NNODES * HC];   // layer input features (x1, x2)
__device__ float g_alpha_s[NNODES * HEADS];
__device__ float g_alpha_d[NNODES * HEADS];
__device__ int   g_src[ETOT];
__device__ int   g_dst[ETOT];
__device__ int   g_deg[NNODES];                // histogram, then scatter cursor
__device__ int   g_rowptr[NNODES + 1];
__device__ int   g_ecsr[ETOT];                 // src ids grouped by dst
__device__ int   g_is64;
__device__ __nv_bfloat16 g_abf[(size_t)NNODES * KP_BIG];  // A' = [Ah|Al|Ah]
__device__ __nv_bfloat16 g_bt[(size_t)HC * KP_BIG];       // B'^T = per out-col [Bh|Bh|Bl]

// ---------------- helpers ----------------
__device__ __forceinline__ uint32_t smem_to_u32(const void* p) {
    uint32_t a;
    asm("{ .reg .u64 t; cvta.to.shared.u64 t, %1; cvt.u32.u64 %0, t; }" : "=r"(a) : "l"(p));
    return a;
}

// ---------------- edge index ----------------
__global__ void detect_dtype_kernel(const int* __restrict__ w) {
    if (threadIdx.x == 0 && blockIdx.x == 0) {
        int is64 = 1;
        #pragma unroll 1
        for (int i = 1; i < 2048; i += 2) if (w[i] != 0) { is64 = 0; break; }
        g_is64 = is64;
    }
}
__global__ void edge_conv_kernel(const void* __restrict__ eiv) {
    int i = blockIdx.x * blockDim.x + threadIdx.x;
    bool is64 = (g_is64 != 0);
    if (i < E0) {
        int s, d;
        if (is64) {
            const long long* e = (const long long*)eiv;
            s = (int)e[i]; d = (int)e[E0 + i];
        } else {
            const int* e = (const int*)eiv;
            s = e[i]; d = e[E0 + i];
        }
        g_src[i] = s; g_dst[i] = d;
    } else if (i < ETOT) {
        int n = i - E0;
        g_src[i] = n; g_dst[i] = n;
    }
}

// ---------------- CSR build (once; reused by all 3 layers) ----------------
__global__ void zero_deg_kernel() {
    int i = blockIdx.x * blockDim.x + threadIdx.x;
    if (i < NNODES) g_deg[i] = 0;
}
__global__ void hist_kernel() {
    int e = blockIdx.x * blockDim.x + threadIdx.x;
    if (e < ETOT) atomicAdd(&g_deg[g_dst[e]], 1);
}
#define SCAN_T 1024
__global__ void scan_kernel() {
    __shared__ int sdata[SCAN_T];
    __shared__ int soffset;
    int tid = threadIdx.x;
    if (tid == 0) soffset = 0;
    __syncthreads();
    for (int base = 0; base < NNODES; base += SCAN_T) {
        int i = base + tid;
        int v = (i < NNODES) ? g_deg[i] : 0;
        sdata[tid] = v;
        __syncthreads();
        #pragma unroll 1
        for (int off = 1; off < SCAN_T; off <<= 1) {
            int t = (tid >= off) ? sdata[tid - off] : 0;
            __syncthreads();
            sdata[tid] += t;
            __syncthreads();
        }
        int incl = sdata[tid];
        if (i < NNODES) g_rowptr[i] = soffset + incl - v;
        __syncthreads();
        if (tid == SCAN_T - 1) soffset += incl;
        __syncthreads();
    }
    if (tid == 0) g_rowptr[NNODES] = soffset;
}
__global__ void scatter_kernel() {
    int e = blockIdx.x * blockDim.x + threadIdx.x;
    if (e >= ETOT) return;
    int d = g_dst[e];
    int pos = g_rowptr[d] + atomicAdd(&g_deg[d], 1);
    g_ecsr[pos] = g_src[e];
}

// ---------------- bf16 split prep ----------------
__global__ void split_a_kernel(const float* __restrict__ X, int K, int Kp) {
    size_t t = (size_t)blockIdx.x * blockDim.x + threadIdx.x;
    size_t total = (size_t)NNODES * K;
    if (t >= total) return;
    int m = (int)(t / K), k = (int)(t % K);
    float v = X[t];
    __nv_bfloat16 hi = __float2bfloat16(v);
    __nv_bfloat16 lo = __float2bfloat16(v - __bfloat162float(hi));
    __nv_bfloat16* row = g_abf + (size_t)m * Kp;
    row[k] = hi; row[K + k] = lo; row[2 * K + k] = hi;
}
__global__ void split_a_small_kernel(const float* __restrict__ X, int K, int Kp) {
    size_t t = (size_t)blockIdx.x * blockDim.x + threadIdx.x;
    size_t total = (size_t)NNODES * Kp;
    if (t >= total) return;
    int m = (int)(t / Kp), c = (int)(t % Kp);
    __nv_bfloat16 o = __float2bfloat16(0.0f);
    if (c < K) {
        o = __float2bfloat16(X[(size_t)m * K + c]);
    } else if (c < 2 * K) {
        float v = X[(size_t)m * K + (c - K)];
        __nv_bfloat16 hi = __float2bfloat16(v);
        o = __float2bfloat16(v - __bfloat162float(hi));
    } else if (c < 3 * K) {
        o = __float2bfloat16(X[(size_t)m * K + (c - 2 * K)]);
    }
    g_abf[t] = o;
}
__global__ void split_b_kernel(const float* __restrict__ W, int K, int Kp) {
    int t = blockIdx.x * blockDim.x + threadIdx.x;
    int total = HC * Kp;
    if (t >= total) return;
    int n = t / Kp, c = t % Kp;
    __nv_bfloat16 o = __float2bfloat16(0.0f);
    if (c < 2 * K) {
        int k = (c < K) ? c : (c - K);
        o = __float2bfloat16(W[(size_t)k * HC + n]);
    } else if (c < 3 * K) {
        float v = W[(size_t)(c - 2 * K) * HC + n];
        __nv_bfloat16 hi = __float2bfloat16(v);
        o = __float2bfloat16(v - __bfloat162float(hi));
    }
    g_bt[t] = o;
}

// ---------------- mma.sync bf16 GEMM: C[M,512] = A'[M,Kp] x (Bt[512,Kp])^T ----------------
#define STAGES 3
#define GBK 32
#define ROWB 80
#define STAGE_A 10240
#define STAGE_BYTES 20480
#define GSMEM (STAGES * STAGE_BYTES)   // 61440

__device__ __forceinline__ void cp_async16(uint32_t dst, const void* src, int src_size) {
    asm volatile("cp.async.cg.shared.global [%0], [%1], 16, %2;"
                 :: "r"(dst), "l"(src), "r"(src_size) : "memory");
}

__global__ void __launch_bounds__(256) mma_gemm_kernel(
    const __nv_bfloat16* __restrict__ A,
    const __nv_bfloat16* __restrict__ Bt,
    float* __restrict__ C, int M, int Kp)
{
    extern __shared__ char smem[];
    uint32_t sb = smem_to_u32(smem);
    int tid = threadIdx.x, wid = tid >> 5, lane = tid & 31;
    int m0 = blockIdx.y * 128, n0 = blockIdx.x * 128;
    int wm = (wid >> 2) * 64, wn = (wid & 3) * 32;
    int g = lane >> 2, q = lane & 3;

    float acc[4][4][4];
    #pragma unroll
    for (int a = 0; a < 4; a++)
        #pragma unroll
        for (int b = 0; b < 4; b++)
            #pragma unroll
            for (int c = 0; c < 4; c++) acc[a][b][c] = 0.0f;

    const int T = Kp / GBK;

    auto issue = [&](int t, int s) {
        uint32_t sa = sb + s * STAGE_BYTES;
        uint32_t sB = sa + STAGE_A;
        int k0 = t * GBK;
        #pragma unroll
        for (int i = 0; i < 2; i++) {
            int idx = i * 256 + tid;
            int r = idx >> 2, c = idx & 3;
            int sz = (m0 + r) < M ? 16 : 0;
            cp_async16(sa + r * ROWB + c * 16, A + (size_t)(m0 + r) * Kp + k0 + c * 8, sz);
            cp_async16(sB + r * ROWB + c * 16, Bt + (size_t)(n0 + r) * Kp + k0 + c * 8, 16);
        }
        asm volatile("cp.async.commit_group;" ::: "memory");
    };

    int pre = (STAGES - 1 < T) ? STAGES - 1 : T;
    for (int s = 0; s < pre; s++) issue(s, s);

    for (int t = 0; t < T; t++) {
        asm volatile("cp.async.wait_group %0;" :: "n"(STAGES - 2));
        __syncthreads();
        if (t + STAGES - 1 < T) {
            issue(t + STAGES - 1, (t + STAGES - 1) % STAGES);
        } else {
            asm volatile("cp.async.commit_group;" ::: "memory");
        }

        uint32_t sa = sb + (t % STAGES) * STAGE_BYTES;
        uint32_t sB = sa + STAGE_A;
        #pragma unroll
        for (int ks = 0; ks < 2; ks++) {
            int kb = ks * 16;
            uint32_t ar[4][4], br[4][2];
            #pragma unroll
            for (int mi = 0; mi < 4; mi++) {
                uint32_t base = sa + (wm + mi * 16 + g) * ROWB + (kb + q * 2) * 2;
                asm volatile("ld.shared.b32 %0, [%1];" : "=r"(ar[mi][0]) : "r"(base));
                asm volatile("ld.shared.b32 %0, [%1];" : "=r"(ar[mi][1]) : "r"(base + 8 * ROWB));
                asm volatile("ld.shared.b32 %0, [%1];" : "=r"(ar[mi][2]) : "r"(base + 16));
                asm volatile("ld.shared.b32 %0, [%1];" : "=r"(ar[mi][3]) : "r"(base + 8 * ROWB + 16));
            }
            #pragma unroll
            for (int ni = 0; ni < 4; ni++) {
                uint32_t base = sB + (wn + ni * 8 + g) * ROWB + (kb + q * 2) * 2;
                asm volatile("ld.shared.b32 %0, [%1];" : "=r"(br[ni][0]) : "r"(base));
                asm volatile("ld.shared.b32 %0, [%1];" : "=r"(br[ni][1]) : "r"(base + 16));
            }
            #pragma unroll
            for (int mi = 0; mi < 4; mi++)
                #pragma unroll
                for (int ni = 0; ni < 4; ni++) {
                    asm volatile(
                        "mma.sync.aligned.m16n8k16.row.col.f32.bf16.bf16.f32 "
                        "{%0,%1,%2,%3}, {%4,%5,%6,%7}, {%8,%9}, {%0,%1,%2,%3};"
                        : "+f"(acc[mi][ni][0]), "+f"(acc[mi][ni][1]),
                          "+f"(acc[mi][ni][2]), "+f"(acc[mi][ni][3])
                        : "r"(ar[mi][0]), "r"(ar[mi][1]), "r"(ar[mi][2]), "r"(ar[mi][3]),
                          "r"(br[ni][0]), "r"(br[ni][1]));
                }
        }
    }

    #pragma unroll
    for (int mi = 0; mi < 4; mi++) {
        int row = m0 + wm + mi * 16 + g;
        #pragma unroll
        for (int ni = 0; ni < 4; ni++) {
            int col = n0 + wn + ni * 8 + q * 2;
            if (row < M)
                *(float2*)&C[(size_t)row * HC + col] = make_float2(acc[mi][ni][0], acc[mi][ni][1]);
            if (row + 8 < M)
                *(float2*)&C[(size_t)(row + 8) * HC + col] = make_float2(acc[mi][ni][2], acc[mi][ni][3]);
        }
    }
}

// ---------------- attention pipeline (CSR, no atomics) ----------------
// Per-node alpha dot products only (no zeroing, no m/denom init).
__global__ void alpha_kernel(const float* __restrict__ a_src,
                             const float* __restrict__ a_dst) {
    int n = blockIdx.x;
    int tid = threadIdx.x;
    int w = tid >> 5, lane = tid & 31;
    const float* hp = g_h + (size_t)n * HC + w * HID;
    float h0 = hp[lane], h1 = hp[lane + 32];
    const float* as = a_src + w * HID;
    const float* ad = a_dst + w * HID;
    float s = h0 * as[lane] + h1 * as[lane + 32];
    float d = h0 * ad[lane] + h1 * ad[lane + 32];
    #pragma unroll
    for (int off = 16; off > 0; off >>= 1) {
        s += __shfl_down_sync(0xFFFFFFFFu, s, off);
        d += __shfl_down_sync(0xFFFFFFFFu, d, off);
    }
    if (lane == 0) {
        g_alpha_s[n * HEADS + w] = s;
        g_alpha_d[n * HEADS + w] = d;
    }
}

// One block per node, warp w = head w. Softmax + weighted gather-sum, direct store.
__global__ void __launch_bounds__(256) gat_aggr_kernel() {
    int n = blockIdx.x;
    int tid = threadIdx.x;
    int w = tid >> 5, lane = tid & 31;
    int beg = g_rowptr[n], end = g_rowptr[n + 1];
    float ad = g_alpha_d[n * HEADS + w];

    // pass 1: max
    float mx = -INFINITY;
    for (int i = beg + lane; i < end; i += 32) {
        int src = g_ecsr[i];
        float v = g_alpha_s[src * HEADS + w] + ad;
        v = v > 0.0f ? v : NEG_SLOPE * v;
        mx = fmaxf(mx, v);
    }
    #pragma unroll
    for (int off = 16; off > 0; off >>= 1)
        mx = fmaxf(mx, __shfl_xor_sync(0xFFFFFFFFu, mx, off));

    // pass 2: denom
    float sum = 0.0f;
    for (int i = beg + lane; i < end; i += 32) {
        int src = g_ecsr[i];
        float v = g_alpha_s[src * HEADS + w] + ad;
        v = v > 0.0f ? v : NEG_SLOPE * v;
        sum += expf(v - mx);
    }
    #pragma unroll
    for (int off = 16; off > 0; off >>= 1)
        sum += __shfl_xor_sync(0xFFFFFFFFu, sum, off);
    float inv = 1.0f / (sum + EPS_DENOM);

    // pass 3: weighted accumulation (sequential over edges; uniform per-edge scalar)
    float acc0 = 0.0f, acc1 = 0.0f;
    for (int i = beg; i < end; i++) {
        int src = g_ecsr[i];                    // broadcast load
        float v = g_alpha_s[src * HEADS + w] + ad;
        v = v > 0.0f ? v : NEG_SLOPE * v;
        float a = expf(v - mx) * inv;
        const float* hrow = g_h + (size_t)src * HC + w * HID;
        acc0 += a * hrow[lane];
        acc1 += a * hrow[lane + 32];
    }
    float* op = g_out + (size_t)n * HC + w * HID;
    op[lane] = acc0;
    op[lane + 32] = acc1;
}

__global__ void post_elu_kernel(const float* __restrict__ bias) {
    size_t idx = (size_t)blockIdx.x * blockDim.x + threadIdx.x;
    size_t total = (size_t)NNODES * HC;
    if (idx >= total) return;
    float v = g_out[idx] + bias[idx & (HC - 1)];
    g_xin[idx] = v > 0.0f ? v : expm1f(v);
}

__global__ void final_kernel(const float* __restrict__ b3,
                             const float* __restrict__ W_out,
                             const float* __restrict__ b_out,
                             float* __restrict__ y) {
    __shared__ float x3[HID];
    __shared__ float Wl[HID * F_OUT];
    int n = blockIdx.x;
    int tid = threadIdx.x;  // 64
    for (int i = tid; i < HID * F_OUT; i += HID) Wl[i] = W_out[i];
    const float* p = g_out + (size_t)n * HC + tid;
    float acc = 0.0f;
    #pragma unroll
    for (int h = 0; h < HEADS; h++) acc += p[h * HID];
    x3[tid] = acc * (1.0f / HEADS) + b3[tid];
    __syncthreads();
    if (tid < F_OUT) {
        float s = b_out[tid];
        #pragma unroll
        for (int c = 0; c < HID; c++) s += x3[c] * Wl[c * F_OUT + tid];
        y[(size_t)n * F_OUT + tid] = s;
    }
}

// ---------------- launcher ----------------
extern "C" void kernel_launch(void* const* d_in, const int* in_sizes, int n_in,
                              void* d_out, int out_size) {
    const float* x      = (const float*)d_in[0];
    const void*  ei     = d_in[1];
    const float* W1     = (const float*)d_in[2];
    const float* a1_src = (const float*)d_in[3];
    const float* a1_dst = (const float*)d_in[4];
    const float* b1     = (const float*)d_in[5];
    const float* W2     = (const float*)d_in[6];
    const float* a2_src = (const float*)d_in[7];
    const float* a2_dst = (const float*)d_in[8];
    const float* b2     = (const float*)d_in[9];
    const float* W3     = (const float*)d_in[10];
    const float* a3_src = (const float*)d_in[11];
    const float* a3_dst = (const float*)d_in[12];
    const float* b3     = (const float*)d_in[13];
    const float* W_out  = (const float*)d_in[14];
    const float* b_out  = (const float*)d_in[15];
    float*       y      = (float*)d_out;

    float *p_h, *p_xin;
    __nv_bfloat16 *p_abf, *p_bt;
    cudaGetSymbolAddress((void**)&p_h, g_h);
    cudaGetSymbolAddress((void**)&p_xin, g_xin);
    cudaGetSymbolAddress((void**)&p_abf, g_abf);
    cudaGetSymbolAddress((void**)&p_bt, g_bt);

    cudaFuncSetAttribute(mma_gemm_kernel, cudaFuncAttributeMaxDynamicSharedMemorySize, GSMEM);

    const int edge_blocks = (ETOT + 255) / 256;
    const int node_blocks = (NNODES + 255) / 256;

    // edge conversion + CSR build (once; shared by all 3 layers)
    detect_dtype_kernel<<<1, 32>>>((const int*)ei);
    edge_conv_kernel<<<edge_blocks, 256>>>(ei);
    zero_deg_kernel<<<node_blocks, 256>>>();
    hist_kernel<<<edge_blocks, 256>>>();
    scan_kernel<<<1, SCAN_T>>>();
    zero_deg_kernel<<<node_blocks, 256>>>();
    scatter_kernel<<<edge_blocks, 256>>>();

    const size_t total_nh = (size_t)NNODES * HC;
    const int elu_blocks = (int)((total_nh + 255) / 256);
    dim3 ggrid(HC / 128, (NNODES + 127) / 128);  // (4, 391)

    // ---- layer 1 (K=18, Kp=64) ----
    {
        size_t na = (size_t)NNODES * KP_SMALL;
        split_a_small_kernel<<<(int)((na + 255) / 256), 256>>>(x, F_IN, KP_SMALL);
        split_b_kernel<<<(HC * KP_SMALL + 255) / 256, 256>>>(W1, F_IN, KP_SMALL);
        mma_gemm_kernel<<<ggrid, 256, GSMEM>>>(p_abf, p_bt, p_h, NNODES, KP_SMALL);
    }
    alpha_kernel<<<NNODES, 256>>>(a1_src, a1_dst);
    gat_aggr_kernel<<<NNODES, 256>>>();
    post_elu_kernel<<<elu_blocks, 256>>>(b1);

    // ---- layer 2 (K=512, Kp=1536) ----
    {
        size_t na = (size_t)NNODES * HC;
        split_a_kernel<<<(int)((na + 255) / 256), 256>>>(p_xin, HC, KP_BIG);
        split_b_kernel<<<(HC * KP_BIG + 255) / 256, 256>>>(W2, HC, KP_BIG);
        mma_gemm_kernel<<<ggrid, 256, GSMEM>>>(p_abf, p_bt, p_h, NNODES, KP_BIG);
    }
    alpha_kernel<<<NNODES, 256>>>(a2_src, a2_dst);
    gat_aggr_kernel<<<NNODES, 256>>>();
    post_elu_kernel<<<elu_blocks, 256>>>(b2);

    // ---- layer 3 (K=512, Kp=1536) ----
    {
        size_t na = (size_t)NNODES * HC;
        split_a_kernel<<<(int)((na + 255) / 256), 256>>>(p_xin, HC, KP_BIG);
        split_b_kernel<<<(HC * KP_BIG + 255) / 256, 256>>>(W3, HC, KP_BIG);
        mma_gemm_kernel<<<ggrid, 256, GSMEM>>>(p_abf, p_bt, p_h, NNODES, KP_BIG);
    }
    alpha_kernel<<<NNODES, 256>>>(a3_src, a3_dst);
    gat_aggr_kernel<<<NNODES, 256>>>();
    final_kernel<<<NNODES, HID>>>(b3, W_out, b_out, y);
}

// round 15
// speedup vs baseline: 2.9833x; 1.2020x over previous
#include <cuda_runtime.h>
#include <cuda_bf16.h>
#include <math.h>
#include <cstdint>

// Problem constants
#define NNODES 50000
#define E0     400000
#define ETOT   (E0 + NNODES)   // 450000 with self loops
#define HEADS  8
#define HID    64
#define HC     512             // HEADS*HID
#define F_IN   18
#define F_OUT  15
#define NEG_SLOPE 0.2f
#define EPS_DENOM 1e-16f
#define KP_BIG 1536            // 3*512 augmented-K for bf16 split
#define KP_SMALL 64            // 3*18=54 padded to 64

// ---------------- device scratch (no runtime allocs allowed) ----------------
__device__ float g_h[(size_t)NNODES * HC];     // h = x @ W (per layer)
__device__ float g_out[(size_t)NNODES * HC];   // layer-3 aggregated output
__device__ float g_alpha_s[NNODES * HEADS];
__device__ float g_alpha_d[NNODES * HEADS];
__device__ int   g_src[ETOT];
__device__ int   g_dst[ETOT];
__device__ int   g_deg[NNODES];                // histogram, then scatter cursor
__device__ int   g_rowptr[NNODES + 1];
__device__ int   g_ecsr[ETOT];                 // src ids grouped by dst
__device__ int   g_is64;
__device__ __nv_bfloat16 g_abf[(size_t)NNODES * KP_BIG];  // A' = [Ah|Al|Ah]
__device__ __nv_bfloat16 g_bt[(size_t)HC * KP_BIG];       // B'^T = per out-col [Bh|Bh|Bl]

// ---------------- helpers ----------------
__device__ __forceinline__ uint32_t smem_to_u32(const void* p) {
    uint32_t a;
    asm("{ .reg .u64 t; cvta.to.shared.u64 t, %1; cvt.u32.u64 %0, t; }" : "=r"(a) : "l"(p));
    return a;
}

// ---------------- edge index ----------------
__global__ void detect_dtype_kernel(const int* __restrict__ w) {
    if (threadIdx.x == 0 && blockIdx.x == 0) {
        int is64 = 1;
        #pragma unroll 1
        for (int i = 1; i < 2048; i += 2) if (w[i] != 0) { is64 = 0; break; }
        g_is64 = is64;
    }
}
__global__ void edge_conv_kernel(const void* __restrict__ eiv) {
    int i = blockIdx.x * blockDim.x + threadIdx.x;
    bool is64 = (g_is64 != 0);
    if (i < E0) {
        int s, d;
        if (is64) {
            const long long* e = (const long long*)eiv;
            s = (int)e[i]; d = (int)e[E0 + i];
        } else {
            const int* e = (const int*)eiv;
            s = e[i]; d = e[E0 + i];
        }
        g_src[i] = s; g_dst[i] = d;
    } else if (i < ETOT) {
        int n = i - E0;
        g_src[i] = n; g_dst[i] = n;
    }
}

// ---------------- CSR build (once; reused by all 3 layers) ----------------
__global__ void zero_deg_kernel() {
    int i = blockIdx.x * blockDim.x + threadIdx.x;
    if (i < NNODES) g_deg[i] = 0;
}
__global__ void hist_kernel() {
    int e = blockIdx.x * blockDim.x + threadIdx.x;
    if (e < ETOT) atomicAdd(&g_deg[g_dst[e]], 1);
}
#define SCAN_T 1024
__global__ void scan_kernel() {
    __shared__ int sdata[SCAN_T];
    __shared__ int soffset;
    int tid = threadIdx.x;
    if (tid == 0) soffset = 0;
    __syncthreads();
    for (int base = 0; base < NNODES; base += SCAN_T) {
        int i = base + tid;
        int v = (i < NNODES) ? g_deg[i] : 0;
        sdata[tid] = v;
        __syncthreads();
        #pragma unroll 1
        for (int off = 1; off < SCAN_T; off <<= 1) {
            int t = (tid >= off) ? sdata[tid - off] : 0;
            __syncthreads();
            sdata[tid] += t;
            __syncthreads();
        }
        int incl = sdata[tid];
        if (i < NNODES) g_rowptr[i] = soffset + incl - v;
        __syncthreads();
        if (tid == SCAN_T - 1) soffset += incl;
        __syncthreads();
    }
    if (tid == 0) g_rowptr[NNODES] = soffset;
}
__global__ void scatter_kernel() {
    int e = blockIdx.x * blockDim.x + threadIdx.x;
    if (e >= ETOT) return;
    int d = g_dst[e];
    int pos = g_rowptr[d] + atomicAdd(&g_deg[d], 1);
    g_ecsr[pos] = g_src[e];
}

// ---------------- bf16 split prep (layer 1 input + weights) ----------------
__global__ void split_a_small_kernel(const float* __restrict__ X, int K, int Kp) {
    size_t t = (size_t)blockIdx.x * blockDim.x + threadIdx.x;
    size_t total = (size_t)NNODES * Kp;
    if (t >= total) return;
    int m = (int)(t / Kp), c = (int)(t % Kp);
    __nv_bfloat16 o = __float2bfloat16(0.0f);
    if (c < K) {
        o = __float2bfloat16(X[(size_t)m * K + c]);
    } else if (c < 2 * K) {
        float v = X[(size_t)m * K + (c - K)];
        __nv_bfloat16 hi = __float2bfloat16(v);
        o = __float2bfloat16(v - __bfloat162float(hi));
    } else if (c < 3 * K) {
        o = __float2bfloat16(X[(size_t)m * K + (c - 2 * K)]);
    }
    g_abf[t] = o;
}
__global__ void split_b_kernel(const float* __restrict__ W, int K, int Kp) {
    int t = blockIdx.x * blockDim.x + threadIdx.x;
    int total = HC * Kp;
    if (t >= total) return;
    int n = t / Kp, c = t % Kp;
    __nv_bfloat16 o = __float2bfloat16(0.0f);
    if (c < 2 * K) {
        int k = (c < K) ? c : (c - K);
        o = __float2bfloat16(W[(size_t)k * HC + n]);
    } else if (c < 3 * K) {
        float v = W[(size_t)(c - 2 * K) * HC + n];
        __nv_bfloat16 hi = __float2bfloat16(v);
        o = __float2bfloat16(v - __bfloat162float(hi));
    }
    g_bt[t] = o;
}

// ---------------- mma.sync bf16 GEMM: C[M,512] = A'[M,Kp] x (Bt[512,Kp])^T ----------------
#define STAGES 3
#define GBK 32
#define ROWB 80
#define STAGE_A 10240
#define STAGE_BYTES 20480
#define GSMEM (STAGES * STAGE_BYTES)   // 61440

__device__ __forceinline__ void cp_async16(uint32_t dst, const void* src, int src_size) {
    asm volatile("cp.async.cg.shared.global [%0], [%1], 16, %2;"
                 :: "r"(dst), "l"(src), "r"(src_size) : "memory");
}

__global__ void __launch_bounds__(256) mma_gemm_kernel(
    const __nv_bfloat16* __restrict__ A,
    const __nv_bfloat16* __restrict__ Bt,
    float* __restrict__ C, int M, int Kp)
{
    extern __shared__ char smem[];
    uint32_t sb = smem_to_u32(smem);
    int tid = threadIdx.x, wid = tid >> 5, lane = tid & 31;
    int m0 = blockIdx.y * 128, n0 = blockIdx.x * 128;
    int wm = (wid >> 2) * 64, wn = (wid & 3) * 32;
    int g = lane >> 2, q = lane & 3;

    float acc[4][4][4];
    #pragma unroll
    for (int a = 0; a < 4; a++)
        #pragma unroll
        for (int b = 0; b < 4; b++)
            #pragma unroll
            for (int c = 0; c < 4; c++) acc[a][b][c] = 0.0f;

    const int T = Kp / GBK;

    auto issue = [&](int t, int s) {
        uint32_t sa = sb + s * STAGE_BYTES;
        uint32_t sB = sa + STAGE_A;
        int k0 = t * GBK;
        #pragma unroll
        for (int i = 0; i < 2; i++) {
            int idx = i * 256 + tid;
            int r = idx >> 2, c = idx & 3;
            int sz = (m0 + r) < M ? 16 : 0;
            cp_async16(sa + r * ROWB + c * 16, A + (size_t)(m0 + r) * Kp + k0 + c * 8, sz);
            cp_async16(sB + r * ROWB + c * 16, Bt + (size_t)(n0 + r) * Kp + k0 + c * 8, 16);
        }
        asm volatile("cp.async.commit_group;" ::: "memory");
    };

    int pre = (STAGES - 1 < T) ? STAGES - 1 : T;
    for (int s = 0; s < pre; s++) issue(s, s);

    for (int t = 0; t < T; t++) {
        asm volatile("cp.async.wait_group %0;" :: "n"(STAGES - 2));
        __syncthreads();
        if (t + STAGES - 1 < T) {
            issue(t + STAGES - 1, (t + STAGES - 1) % STAGES);
        } else {
            asm volatile("cp.async.commit_group;" ::: "memory");
        }

        uint32_t sa = sb + (t % STAGES) * STAGE_BYTES;
        uint32_t sB = sa + STAGE_A;
        #pragma unroll
        for (int ks = 0; ks < 2; ks++) {
            int kb = ks * 16;
            uint32_t ar[4][4], br[4][2];
            #pragma unroll
            for (int mi = 0; mi < 4; mi++) {
                uint32_t base = sa + (wm + mi * 16 + g) * ROWB + (kb + q * 2) * 2;
                asm volatile("ld.shared.b32 %0, [%1];" : "=r"(ar[mi][0]) : "r"(base));
                asm volatile("ld.shared.b32 %0, [%1];" : "=r"(ar[mi][1]) : "r"(base + 8 * ROWB));
                asm volatile("ld.shared.b32 %0, [%1];" : "=r"(ar[mi][2]) : "r"(base + 16));
                asm volatile("ld.shared.b32 %0, [%1];" : "=r"(ar[mi][3]) : "r"(base + 8 * ROWB + 16));
            }
            #pragma unroll
            for (int ni = 0; ni < 4; ni++) {
                uint32_t base = sB + (wn + ni * 8 + g) * ROWB + (kb + q * 2) * 2;
                asm volatile("ld.shared.b32 %0, [%1];" : "=r"(br[ni][0]) : "r"(base));
                asm volatile("ld.shared.b32 %0, [%1];" : "=r"(br[ni][1]) : "r"(base + 16));
            }
            #pragma unroll
            for (int mi = 0; mi < 4; mi++)
                #pragma unroll
                for (int ni = 0; ni < 4; ni++) {
                    asm volatile(
                        "mma.sync.aligned.m16n8k16.row.col.f32.bf16.bf16.f32 "
                        "{%0,%1,%2,%3}, {%4,%5,%6,%7}, {%8,%9}, {%0,%1,%2,%3};"
                        : "+f"(acc[mi][ni][0]), "+f"(acc[mi][ni][1]),
                          "+f"(acc[mi][ni][2]), "+f"(acc[mi][ni][3])
                        : "r"(ar[mi][0]), "r"(ar[mi][1]), "r"(ar[mi][2]), "r"(ar[mi][3]),
                          "r"(br[ni][0]), "r"(br[ni][1]));
                }
        }
    }

    #pragma unroll
    for (int mi = 0; mi < 4; mi++) {
        int row = m0 + wm + mi * 16 + g;
        #pragma unroll
        for (int ni = 0; ni < 4; ni++) {
            int col = n0 + wn + ni * 8 + q * 2;
            if (row < M)
                *(float2*)&C[(size_t)row * HC + col] = make_float2(acc[mi][ni][0], acc[mi][ni][1]);
            if (row + 8 < M)
                *(float2*)&C[(size_t)(row + 8) * HC + col] = make_float2(acc[mi][ni][2], acc[mi][ni][3]);
        }
    }
}

// ---------------- attention pipeline (CSR, no atomics) ----------------
__global__ void alpha_kernel(const float* __restrict__ a_src,
                             const float* __restrict__ a_dst) {
    int n = blockIdx.x;
    int tid = threadIdx.x;
    int w = tid >> 5, lane = tid & 31;
    const float* hp = g_h + (size_t)n * HC + w * HID;
    float h0 = hp[lane], h1 = hp[lane + 32];
    const float* as = a_src + w * HID;
    const float* ad = a_dst + w * HID;
    float s = h0 * as[lane] + h1 * as[lane + 32];
    float d = h0 * ad[lane] + h1 * ad[lane + 32];
    #pragma unroll
    for (int off = 16; off > 0; off >>= 1) {
        s += __shfl_down_sync(0xFFFFFFFFu, s, off);
        d += __shfl_down_sync(0xFFFFFFFFu, d, off);
    }
    if (lane == 0) {
        g_alpha_s[n * HEADS + w] = s;
        g_alpha_d[n * HEADS + w] = d;
    }
}

// One block per node, warp w = head w. Softmax + weighted gather-sum.
// mode 1 (layers 1-2): epilogue = +bias, ELU, bf16 [hi|lo|hi] split into g_abf.
// mode 0 (layer 3):    raw float store to g_out.
__global__ void __launch_bounds__(256) gat_aggr_kernel(const float* __restrict__ bias, int mode) {
    int n = blockIdx.x;
    int tid = threadIdx.x;
    int w = tid >> 5, lane = tid & 31;
    int beg = g_rowptr[n], end = g_rowptr[n + 1];
    float ad = g_alpha_d[n * HEADS + w];

    // pass 1: max
    float mx = -INFINITY;
    for (int i = beg + lane; i < end; i += 32) {
        int src = g_ecsr[i];
        float v = g_alpha_s[src * HEADS + w] + ad;
        v = v > 0.0f ? v : NEG_SLOPE * v;
        mx = fmaxf(mx, v);
    }
    #pragma unroll
    for (int off = 16; off > 0; off >>= 1)
        mx = fmaxf(mx, __shfl_xor_sync(0xFFFFFFFFu, mx, off));

    // pass 2: denom
    float sum = 0.0f;
    for (int i = beg + lane; i < end; i += 32) {
        int src = g_ecsr[i];
        float v = g_alpha_s[src * HEADS + w] + ad;
        v = v > 0.0f ? v : NEG_SLOPE * v;
        sum += expf(v - mx);
    }
    #pragma unroll
    for (int off = 16; off > 0; off >>= 1)
        sum += __shfl_xor_sync(0xFFFFFFFFu, sum, off);
    float inv = 1.0f / (sum + EPS_DENOM);

    // pass 3: weighted accumulation, 2-way unrolled for load MLP
    float acc0 = 0.0f, acc1 = 0.0f;
    int i = beg;
    for (; i + 1 < end; i += 2) {
        int s0 = g_ecsr[i], s1 = g_ecsr[i + 1];
        float v0 = g_alpha_s[s0 * HEADS + w] + ad;
        float v1 = g_alpha_s[s1 * HEADS + w] + ad;
        v0 = v0 > 0.0f ? v0 : NEG_SLOPE * v0;
        v1 = v1 > 0.0f ? v1 : NEG_SLOPE * v1;
        float a0 = expf(v0 - mx) * inv;
        float a1 = expf(v1 - mx) * inv;
        const float* h0 = g_h + (size_t)s0 * HC + w * HID;
        const float* h1 = g_h + (size_t)s1 * HC + w * HID;
        float x00 = h0[lane], x01 = h0[lane + 32];
        float x10 = h1[lane], x11 = h1[lane + 32];
        acc0 += a0 * x00 + a1 * x10;
        acc1 += a0 * x01 + a1 * x11;
    }
    if (i < end) {
        int s0 = g_ecsr[i];
        float v0 = g_alpha_s[s0 * HEADS + w] + ad;
        v0 = v0 > 0.0f ? v0 : NEG_SLOPE * v0;
        float a0 = expf(v0 - mx) * inv;
        const float* h0 = g_h + (size_t)s0 * HC + w * HID;
        acc0 += a0 * h0[lane];
        acc1 += a0 * h0[lane + 32];
    }

    int k0 = w * HID + lane, k1 = k0 + 32;
    if (mode) {
        // fused bias + ELU + bf16 [hi|lo|hi] split into g_abf (next layer's A')
        float v0 = acc0 + bias[k0];
        float v1 = acc1 + bias[k1];
        v0 = v0 > 0.0f ? v0 : expm1f(v0);
        v1 = v1 > 0.0f ? v1 : expm1f(v1);
        __nv_bfloat16 h0 = __float2bfloat16(v0);
        __nv_bfloat16 l0 = __float2bfloat16(v0 - __bfloat162float(h0));
        __nv_bfloat16 h1 = __float2bfloat16(v1);
        __nv_bfloat16 l1 = __float2bfloat16(v1 - __bfloat162float(h1));
        __nv_bfloat16* row = g_abf + (size_t)n * KP_BIG;
        row[k0] = h0;            row[k1] = h1;
        row[HC + k0] = l0;       row[HC + k1] = l1;
        row[2 * HC + k0] = h0;   row[2 * HC + k1] = h1;
    } else {
        float* op = g_out + (size_t)n * HC;
        op[k0] = acc0;
        op[k1] = acc1;
    }
}

__global__ void final_kernel(const float* __restrict__ b3,
                             const float* __restrict__ W_out,
                             const float* __restrict__ b_out,
                             float* __restrict__ y) {
    __shared__ float x3[HID];
    __shared__ float Wl[HID * F_OUT];
    int n = blockIdx.x;
    int tid = threadIdx.x;  // 64
    for (int i = tid; i < HID * F_OUT; i += HID) Wl[i] = W_out[i];
    const float* p = g_out + (size_t)n * HC + tid;
    float acc = 0.0f;
    #pragma unroll
    for (int h = 0; h < HEADS; h++) acc += p[h * HID];
    x3[tid] = acc * (1.0f / HEADS) + b3[tid];
    __syncthreads();
    if (tid < F_OUT) {
        float s = b_out[tid];
        #pragma unroll
        for (int c = 0; c < HID; c++) s += x3[c] * Wl[c * F_OUT + tid];
        y[(size_t)n * F_OUT + tid] = s;
    }
}

// ---------------- launcher ----------------
extern "C" void kernel_launch(void* const* d_in, const int* in_sizes, int n_in,
                              void* d_out, int out_size) {
    const float* x      = (const float*)d_in[0];
    const void*  ei     = d_in[1];
    const float* W1     = (const float*)d_in[2];
    const float* a1_src = (const float*)d_in[3];
    const float* a1_dst = (const float*)d_in[4];
    const float* b1     = (const float*)d_in[5];
    const float* W2     = (const float*)d_in[6];
    const float* a2_src = (const float*)d_in[7];
    const float* a2_dst = (const float*)d_in[8];
    const float* b2     = (const float*)d_in[9];
    const float* W3     = (const float*)d_in[10];
    const float* a3_src = (const float*)d_in[11];
    const float* a3_dst = (const float*)d_in[12];
    const float* b3     = (const float*)d_in[13];
    const float* W_out  = (const float*)d_in[14];
    const float* b_out  = (const float*)d_in[15];
    float*       y      = (float*)d_out;

    float *p_h;
    __nv_bfloat16 *p_abf, *p_bt;
    cudaGetSymbolAddress((void**)&p_h, g_h);
    cudaGetSymbolAddress((void**)&p_abf, g_abf);
    cudaGetSymbolAddress((void**)&p_bt, g_bt);

    cudaFuncSetAttribute(mma_gemm_kernel, cudaFuncAttributeMaxDynamicSharedMemorySize, GSMEM);

    const int edge_blocks = (ETOT + 255) / 256;
    const int node_blocks = (NNODES + 255) / 256;

    // edge conversion + CSR build (once; shared by all 3 layers)
    detect_dtype_kernel<<<1, 32>>>((const int*)ei);
    edge_conv_kernel<<<edge_blocks, 256>>>(ei);
    zero_deg_kernel<<<node_blocks, 256>>>();
    hist_kernel<<<edge_blocks, 256>>>();
    scan_kernel<<<1, SCAN_T>>>();
    zero_deg_kernel<<<node_blocks, 256>>>();
    scatter_kernel<<<edge_blocks, 256>>>();

    dim3 ggrid(HC / 128, (NNODES + 127) / 128);  // (4, 391)

    // ---- layer 1 (K=18, Kp=64) ----
    {
        size_t na = (size_t)NNODES * KP_SMALL;
        split_a_small_kernel<<<(int)((na + 255) / 256), 256>>>(x, F_IN, KP_SMALL);
        split_b_kernel<<<(HC * KP_SMALL + 255) / 256, 256>>>(W1, F_IN, KP_SMALL);
        mma_gemm_kernel<<<ggrid, 256, GSMEM>>>(p_abf, p_bt, p_h, NNODES, KP_SMALL);
    }
    alpha_kernel<<<NNODES, 256>>>(a1_src, a1_dst);
    gat_aggr_kernel<<<NNODES, 256>>>(b1, 1);   // writes bf16 A' for layer 2

    // ---- layer 2 (K=512, Kp=1536) ----
    split_b_kernel<<<(HC * KP_BIG + 255) / 256, 256>>>(W2, HC, KP_BIG);
    mma_gemm_kernel<<<ggrid, 256, GSMEM>>>(p_abf, p_bt, p_h, NNODES, KP_BIG);
    alpha_kernel<<<NNODES, 256>>>(a2_src, a2_dst);
    gat_aggr_kernel<<<NNODES, 256>>>(b2, 1);   // writes bf16 A' for layer 3

    // ---- layer 3 (K=512, Kp=1536) ----
    split_b_kernel<<<(HC * KP_BIG + 255) / 256, 256>>>(W3, HC, KP_BIG);
    mma_gemm_kernel<<<ggrid, 256, GSMEM>>>(p_abf, p_bt, p_h, NNODES, KP_BIG);
    alpha_kernel<<<NNODES, 256>>>(a3_src, a3_dst);
    gat_aggr_kernel<<<NNODES, 256>>>(b3, 0);   // raw float to g_out

    final_kernel<<<NNODES, HID>>>(b3, W_out, b_out, y);
}

// round 17
// speedup vs baseline: 3.0966x; 1.0380x over previous
#include <cuda_runtime.h>
#include <cuda_bf16.h>
#include <math.h>
#include <cstdint>

// Problem constants
#define NNODES 50000
#define E0     400000
#define ETOT   (E0 + NNODES)   // 450000 with self loops
#define HEADS  8
#define HID    64
#define HC     512             // HEADS*HID
#define F_IN   18
#define F_OUT  15
#define NEG_SLOPE 0.2f
#define EPS_DENOM 1e-16f
#define KP_BIG 1536            // 3*512 augmented-K for bf16 split
#define KP_SMALL 64            // 3*18=54 padded to 64

// ---------------- device scratch (no runtime allocs allowed) ----------------
__device__ float g_h[(size_t)NNODES * HC];     // h = x @ W (per layer)
__device__ float g_out[(size_t)NNODES * HC];   // layer-3 aggregated output
__device__ float g_alpha_s[NNODES * HEADS];
__device__ float g_alpha_d[NNODES * HEADS];
__device__ int   g_src[ETOT];
__device__ int   g_dst[ETOT];
__device__ int   g_deg[NNODES];                // histogram, then scatter cursor
__device__ int   g_rowptr[NNODES + 1];
__device__ int   g_ecsr[ETOT];                 // src ids grouped by dst
__device__ int   g_is64;
__device__ __nv_bfloat16 g_abf[(size_t)NNODES * KP_BIG];  // A' = [Ah|Al|Ah]
__device__ __nv_bfloat16 g_bt[(size_t)HC * KP_BIG];       // B'^T = per out-col [Bh|Bh|Bl]

// ---------------- helpers ----------------
__device__ __forceinline__ uint32_t smem_to_u32(const void* p) {
    uint32_t a;
    asm("{ .reg .u64 t; cvta.to.shared.u64 t, %1; cvt.u32.u64 %0, t; }" : "=r"(a) : "l"(p));
    return a;
}

// ---------------- edge index ----------------
__global__ void detect_dtype_kernel(const int* __restrict__ w) {
    if (threadIdx.x == 0 && blockIdx.x == 0) {
        int is64 = 1;
        #pragma unroll 1
        for (int i = 1; i < 2048; i += 2) if (w[i] != 0) { is64 = 0; break; }
        g_is64 = is64;
    }
}
__global__ void edge_conv_kernel(const void* __restrict__ eiv) {
    int i = blockIdx.x * blockDim.x + threadIdx.x;
    bool is64 = (g_is64 != 0);
    if (i < E0) {
        int s, d;
        if (is64) {
            const long long* e = (const long long*)eiv;
            s = (int)e[i]; d = (int)e[E0 + i];
        } else {
            const int* e = (const int*)eiv;
            s = e[i]; d = e[E0 + i];
        }
        g_src[i] = s; g_dst[i] = d;
    } else if (i < ETOT) {
        int n = i - E0;
        g_src[i] = n; g_dst[i] = n;
    }
}

// ---------------- CSR build (once; reused by all 3 layers) ----------------
__global__ void zero_deg_kernel() {
    int i = blockIdx.x * blockDim.x + threadIdx.x;
    if (i < NNODES) g_deg[i] = 0;
}
__global__ void hist_kernel() {
    int e = blockIdx.x * blockDim.x + threadIdx.x;
    if (e < ETOT) atomicAdd(&g_deg[g_dst[e]], 1);
}
#define SCAN_T 1024
__global__ void scan_kernel() {
    __shared__ int sdata[SCAN_T];
    __shared__ int soffset;
    int tid = threadIdx.x;
    if (tid == 0) soffset = 0;
    __syncthreads();
    for (int base = 0; base < NNODES; base += SCAN_T) {
        int i = base + tid;
        int v = (i < NNODES) ? g_deg[i] : 0;
        sdata[tid] = v;
        __syncthreads();
        #pragma unroll 1
        for (int off = 1; off < SCAN_T; off <<= 1) {
            int t = (tid >= off) ? sdata[tid - off] : 0;
            __syncthreads();
            sdata[tid] += t;
            __syncthreads();
        }
        int incl = sdata[tid];
        if (i < NNODES) g_rowptr[i] = soffset + incl - v;
        __syncthreads();
        if (tid == SCAN_T - 1) soffset += incl;
        __syncthreads();
    }
    if (tid == 0) g_rowptr[NNODES] = soffset;
}
__global__ void scatter_kernel() {
    int e = blockIdx.x * blockDim.x + threadIdx.x;
    if (e >= ETOT) return;
    int d = g_dst[e];
    int pos = g_rowptr[d] + atomicAdd(&g_deg[d], 1);
    g_ecsr[pos] = g_src[e];
}

// ---------------- bf16 split prep (layer 1 input + weights) ----------------
__global__ void split_a_small_kernel(const float* __restrict__ X, int K, int Kp) {
    size_t t = (size_t)blockIdx.x * blockDim.x + threadIdx.x;
    size_t total = (size_t)NNODES * Kp;
    if (t >= total) return;
    int m = (int)(t / Kp), c = (int)(t % Kp);
    __nv_bfloat16 o = __float2bfloat16(0.0f);
    if (c < K) {
        o = __float2bfloat16(X[(size_t)m * K + c]);
    } else if (c < 2 * K) {
        float v = X[(size_t)m * K + (c - K)];
        __nv_bfloat16 hi = __float2bfloat16(v);
        o = __float2bfloat16(v - __bfloat162float(hi));
    } else if (c < 3 * K) {
        o = __float2bfloat16(X[(size_t)m * K + (c - 2 * K)]);
    }
    g_abf[t] = o;
}
__global__ void split_b_kernel(const float* __restrict__ W, int K, int Kp) {
    int t = blockIdx.x * blockDim.x + threadIdx.x;
    int total = HC * Kp;
    if (t >= total) return;
    int n = t / Kp, c = t % Kp;
    __nv_bfloat16 o = __float2bfloat16(0.0f);
    if (c < 2 * K) {
        int k = (c < K) ? c : (c - K);
        o = __float2bfloat16(W[(size_t)k * HC + n]);
    } else if (c < 3 * K) {
        float v = W[(size_t)(c - 2 * K) * HC + n];
        __nv_bfloat16 hi = __float2bfloat16(v);
        o = __float2bfloat16(v - __bfloat162float(hi));
    }
    g_bt[t] = o;
}

// ---------------- mma.sync bf16 GEMM + fused alpha dot products ----------------
#define STAGES 3
#define GBK 32
#define ROWB 80
#define STAGE_A 10240
#define STAGE_BYTES 20480
#define GSMEM (STAGES * STAGE_BYTES)   // 61440

__device__ __forceinline__ void cp_async16(uint32_t dst, const void* src, int src_size) {
    asm volatile("cp.async.cg.shared.global [%0], [%1], 16, %2;"
                 :: "r"(dst), "l"(src), "r"(src_size) : "memory");
}

__global__ void __launch_bounds__(256) mma_gemm_kernel(
    const __nv_bfloat16* __restrict__ A,
    const __nv_bfloat16* __restrict__ Bt,
    float* __restrict__ C, int M, int Kp,
    const float* __restrict__ a_src, const float* __restrict__ a_dst,
    float* __restrict__ alpha_s, float* __restrict__ alpha_d)
{
    extern __shared__ char smem[];
    uint32_t sb = smem_to_u32(smem);
    int tid = threadIdx.x, wid = tid >> 5, lane = tid & 31;
    int m0 = blockIdx.y * 128, n0 = blockIdx.x * 128;
    int wm = (wid >> 2) * 64, wn = (wid & 3) * 32;
    int g = lane >> 2, q = lane & 3;

    float acc[4][4][4];
    #pragma unroll
    for (int a = 0; a < 4; a++)
        #pragma unroll
        for (int b = 0; b < 4; b++)
            #pragma unroll
            for (int c = 0; c < 4; c++) acc[a][b][c] = 0.0f;

    const int T = Kp / GBK;

    auto issue = [&](int t, int s) {
        uint32_t sa = sb + s * STAGE_BYTES;
        uint32_t sB = sa + STAGE_A;
        int k0 = t * GBK;
        #pragma unroll
        for (int i = 0; i < 2; i++) {
            int idx = i * 256 + tid;
            int r = idx >> 2, c = idx & 3;
            int sz = (m0 + r) < M ? 16 : 0;
            cp_async16(sa + r * ROWB + c * 16, A + (size_t)(m0 + r) * Kp + k0 + c * 8, sz);
            cp_async16(sB + r * ROWB + c * 16, Bt + (size_t)(n0 + r) * Kp + k0 + c * 8, 16);
        }
        asm volatile("cp.async.commit_group;" ::: "memory");
    };

    int pre = (STAGES - 1 < T) ? STAGES - 1 : T;
    for (int s = 0; s < pre; s++) issue(s, s);

    for (int t = 0; t < T; t++) {
        asm volatile("cp.async.wait_group %0;" :: "n"(STAGES - 2));
        __syncthreads();
        if (t + STAGES - 1 < T) {
            issue(t + STAGES - 1, (t + STAGES - 1) % STAGES);
        } else {
            asm volatile("cp.async.commit_group;" ::: "memory");
        }

        uint32_t sa = sb + (t % STAGES) * STAGE_BYTES;
        uint32_t sB = sa + STAGE_A;
        #pragma unroll
        for (int ks = 0; ks < 2; ks++) {
            int kb = ks * 16;
            uint32_t ar[4][4], br[4][2];
            #pragma unroll
            for (int mi = 0; mi < 4; mi++) {
                uint32_t base = sa + (wm + mi * 16 + g) * ROWB + (kb + q * 2) * 2;
                asm volatile("ld.shared.b32 %0, [%1];" : "=r"(ar[mi][0]) : "r"(base));
                asm volatile("ld.shared.b32 %0, [%1];" : "=r"(ar[mi][1]) : "r"(base + 8 * ROWB));
                asm volatile("ld.shared.b32 %0, [%1];" : "=r"(ar[mi][2]) : "r"(base + 16));
                asm volatile("ld.shared.b32 %0, [%1];" : "=r"(ar[mi][3]) : "r"(base + 8 * ROWB + 16));
            }
            #pragma unroll
            for (int ni = 0; ni < 4; ni++) {
                uint32_t base = sB + (wn + ni * 8 + g) * ROWB + (kb + q * 2) * 2;
                asm volatile("ld.shared.b32 %0, [%1];" : "=r"(br[ni][0]) : "r"(base));
                asm volatile("ld.shared.b32 %0, [%1];" : "=r"(br[ni][1]) : "r"(base + 16));
            }
            #pragma unroll
            for (int mi = 0; mi < 4; mi++)
                #pragma unroll
                for (int ni = 0; ni < 4; ni++) {
                    asm volatile(
                        "mma.sync.aligned.m16n8k16.row.col.f32.bf16.bf16.f32 "
                        "{%0,%1,%2,%3}, {%4,%5,%6,%7}, {%8,%9}, {%0,%1,%2,%3};"
                        : "+f"(acc[mi][ni][0]), "+f"(acc[mi][ni][1]),
                          "+f"(acc[mi][ni][2]), "+f"(acc[mi][ni][3])
                        : "r"(ar[mi][0]), "r"(ar[mi][1]), "r"(ar[mi][2]), "r"(ar[mi][3]),
                          "r"(br[ni][0]), "r"(br[ni][1]));
                }
        }
    }

    // ---- fused alpha partial dot products ----
    // Head of this warp's 32-col range (64-col heads, warp range fully inside one head).
    int head = (n0 + wn) >> 6;
    // per-thread a_src/a_dst values for its 8 columns
    float asv[8], adv[8];
    #pragma unroll
    for (int ni = 0; ni < 4; ni++) {
        int col = n0 + wn + ni * 8 + q * 2;
        asv[ni * 2]     = a_src[col];
        asv[ni * 2 + 1] = a_src[col + 1];
        adv[ni * 2]     = a_dst[col];
        adv[ni * 2 + 1] = a_dst[col + 1];
    }
    #pragma unroll
    for (int mi = 0; mi < 4; mi++) {
        #pragma unroll
        for (int rs = 0; rs < 2; rs++) {
            int row = m0 + wm + mi * 16 + g + rs * 8;
            float sp = 0.0f, dp = 0.0f;
            #pragma unroll
            for (int ni = 0; ni < 4; ni++) {
                sp += acc[mi][ni][rs * 2] * asv[ni * 2] + acc[mi][ni][rs * 2 + 1] * asv[ni * 2 + 1];
                dp += acc[mi][ni][rs * 2] * adv[ni * 2] + acc[mi][ni][rs * 2 + 1] * adv[ni * 2 + 1];
            }
            // quad reduction (lanes q=0..3 share this row)
            sp += __shfl_down_sync(0xFFFFFFFFu, sp, 2, 4);
            sp += __shfl_down_sync(0xFFFFFFFFu, sp, 1, 4);
            dp += __shfl_down_sync(0xFFFFFFFFu, dp, 2, 4);
            dp += __shfl_down_sync(0xFFFFFFFFu, dp, 1, 4);
            if (q == 0 && row < M) {
                atomicAdd(&alpha_s[row * HEADS + head], sp);
                atomicAdd(&alpha_d[row * HEADS + head], dp);
            }
        }
    }

    // ---- C stores ----
    #pragma unroll
    for (int mi = 0; mi < 4; mi++) {
        int row = m0 + wm + mi * 16 + g;
        #pragma unroll
        for (int ni = 0; ni < 4; ni++) {
            int col = n0 + wn + ni * 8 + q * 2;
            if (row < M)
                *(float2*)&C[(size_t)row * HC + col] = make_float2(acc[mi][ni][0], acc[mi][ni][1]);
            if (row + 8 < M)
                *(float2*)&C[(size_t)(row + 8) * HC + col] = make_float2(acc[mi][ni][2], acc[mi][ni][3]);
        }
    }
}

// ---------------- attention aggregation (CSR, no atomics) ----------------
// One block per node, warp w = head w. Softmax + weighted gather-sum.
// mode 1 (layers 1-2): epilogue = +bias, ELU, bf16 [hi|lo|hi] split into g_abf.
// mode 0 (layer 3):    raw float store to g_out.
__global__ void __launch_bounds__(256) gat_aggr_kernel(const float* __restrict__ bias, int mode) {
    int n = blockIdx.x;
    int tid = threadIdx.x;
    int w = tid >> 5, lane = tid & 31;
    int beg = g_rowptr[n], end = g_rowptr[n + 1];
    float ad = g_alpha_d[n * HEADS + w];

    // pass 1: max
    float mx = -INFINITY;
    for (int i = beg + lane; i < end; i += 32) {
        int src = g_ecsr[i];
        float v = g_alpha_s[src * HEADS + w] + ad;
        v = v > 0.0f ? v : NEG_SLOPE * v;
        mx = fmaxf(mx, v);
    }
    #pragma unroll
    for (int off = 16; off > 0; off >>= 1)
        mx = fmaxf(mx, __shfl_xor_sync(0xFFFFFFFFu, mx, off));

    // pass 2: denom
    float sum = 0.0f;
    for (int i = beg + lane; i < end; i += 32) {
        int src = g_ecsr[i];
        float v = g_alpha_s[src * HEADS + w] + ad;
        v = v > 0.0f ? v : NEG_SLOPE * v;
        sum += expf(v - mx);
    }
    #pragma unroll
    for (int off = 16; off > 0; off >>= 1)
        sum += __shfl_xor_sync(0xFFFFFFFFu, sum, off);
    float inv = 1.0f / (sum + EPS_DENOM);

    // pass 3: weighted accumulation, 4-way unrolled for load MLP
    float acc0 = 0.0f, acc1 = 0.0f;
    int i = beg;
    for (; i + 3 < end; i += 4) {
        int s0 = g_ecsr[i], s1 = g_ecsr[i + 1], s2 = g_ecsr[i + 2], s3 = g_ecsr[i + 3];
        float v0 = g_alpha_s[s0 * HEADS + w] + ad;
        float v1 = g_alpha_s[s1 * HEADS + w] + ad;
        float v2 = g_alpha_s[s2 * HEADS + w] + ad;
        float v3 = g_alpha_s[s3 * HEADS + w] + ad;
        v0 = v0 > 0.0f ? v0 : NEG_SLOPE * v0;
        v1 = v1 > 0.0f ? v1 : NEG_SLOPE * v1;
        v2 = v2 > 0.0f ? v2 : NEG_SLOPE * v2;
        v3 = v3 > 0.0f ? v3 : NEG_SLOPE * v3;
        float a0 = expf(v0 - mx) * inv;
        float a1 = expf(v1 - mx) * inv;
        float a2 = expf(v2 - mx) * inv;
        float a3 = expf(v3 - mx) * inv;
        const float* h0 = g_h + (size_t)s0 * HC + w * HID;
        const float* h1 = g_h + (size_t)s1 * HC + w * HID;
        const float* h2 = g_h + (size_t)s2 * HC + w * HID;
        const float* h3 = g_h + (size_t)s3 * HC + w * HID;
        float x00 = h0[lane], x01 = h0[lane + 32];
        float x10 = h1[lane], x11 = h1[lane + 32];
        float x20 = h2[lane], x21 = h2[lane + 32];
        float x30 = h3[lane], x31 = h3[lane + 32];
        acc0 += a0 * x00 + a1 * x10 + a2 * x20 + a3 * x30;
        acc1 += a0 * x01 + a1 * x11 + a2 * x21 + a3 * x31;
    }
    for (; i < end; i++) {
        int s0 = g_ecsr[i];
        float v0 = g_alpha_s[s0 * HEADS + w] + ad;
        v0 = v0 > 0.0f ? v0 : NEG_SLOPE * v0;
        float a0 = expf(v0 - mx) * inv;
        const float* h0 = g_h + (size_t)s0 * HC + w * HID;
        acc0 += a0 * h0[lane];
        acc1 += a0 * h0[lane + 32];
    }

    int k0 = w * HID + lane, k1 = k0 + 32;
    if (mode) {
        float v0 = acc0 + bias[k0];
        float v1 = acc1 + bias[k1];
        v0 = v0 > 0.0f ? v0 : expm1f(v0);
        v1 = v1 > 0.0f ? v1 : expm1f(v1);
        __nv_bfloat16 h0 = __float2bfloat16(v0);
        __nv_bfloat16 l0 = __float2bfloat16(v0 - __bfloat162float(h0));
        __nv_bfloat16 h1 = __float2bfloat16(v1);
        __nv_bfloat16 l1 = __float2bfloat16(v1 - __bfloat162float(h1));
        __nv_bfloat16* row = g_abf + (size_t)n * KP_BIG;
        row[k0] = h0;            row[k1] = h1;
        row[HC + k0] = l0;       row[HC + k1] = l1;
        row[2 * HC + k0] = h0;   row[2 * HC + k1] = h1;
    } else {
        float* op = g_out + (size_t)n * HC;
        op[k0] = acc0;
        op[k1] = acc1;
    }
}

__global__ void final_kernel(const float* __restrict__ b3,
                             const float* __restrict__ W_out,
                             const float* __restrict__ b_out,
                             float* __restrict__ y) {
    __shared__ float x3[HID];
    __shared__ float Wl[HID * F_OUT];
    int n = blockIdx.x;
    int tid = threadIdx.x;  // 64
    for (int i = tid; i < HID * F_OUT; i += HID) Wl[i] = W_out[i];
    const float* p = g_out + (size_t)n * HC + tid;
    float acc = 0.0f;
    #pragma unroll
    for (int h = 0; h < HEADS; h++) acc += p[h * HID];
    x3[tid] = acc * (1.0f / HEADS) + b3[tid];
    __syncthreads();
    if (tid < F_OUT) {
        float s = b_out[tid];
        #pragma unroll
        for (int c = 0; c < HID; c++) s += x3[c] * Wl[c * F_OUT + tid];
        y[(size_t)n * F_OUT + tid] = s;
    }
}

// ---------------- launcher ----------------
extern "C" void kernel_launch(void* const* d_in, const int* in_sizes, int n_in,
                              void* d_out, int out_size) {
    const float* x      = (const float*)d_in[0];
    const void*  ei     = d_in[1];
    const float* W1     = (const float*)d_in[2];
    const float* a1_src = (const float*)d_in[3];
    const float* a1_dst = (const float*)d_in[4];
    const float* b1     = (const float*)d_in[5];
    const float* W2     = (const float*)d_in[6];
    const float* a2_src = (const float*)d_in[7];
    const float* a2_dst = (const float*)d_in[8];
    const float* b2     = (const float*)d_in[9];
    const float* W3     = (const float*)d_in[10];
    const float* a3_src = (const float*)d_in[11];
    const float* a3_dst = (const float*)d_in[12];
    const float* b3     = (const float*)d_in[13];
    const float* W_out  = (const float*)d_in[14];
    const float* b_out  = (const float*)d_in[15];
    float*       y      = (float*)d_out;

    float *p_h, *p_as, *p_ad;
    __nv_bfloat16 *p_abf, *p_bt;
    cudaGetSymbolAddress((void**)&p_h, g_h);
    cudaGetSymbolAddress((void**)&p_abf, g_abf);
    cudaGetSymbolAddress((void**)&p_bt, g_bt);
    cudaGetSymbolAddress((void**)&p_as, g_alpha_s);
    cudaGetSymbolAddress((void**)&p_ad, g_alpha_d);

    cudaFuncSetAttribute(mma_gemm_kernel, cudaFuncAttributeMaxDynamicSharedMemorySize, GSMEM);

    const int edge_blocks = (ETOT + 255) / 256;
    const int node_blocks = (NNODES + 255) / 256;
    const size_t alpha_bytes = (size_t)NNODES * HEADS * sizeof(float);

    // edge conversion + CSR build (once; shared by all 3 layers)
    detect_dtype_kernel<<<1, 32>>>((const int*)ei);
    edge_conv_kernel<<<edge_blocks, 256>>>(ei);
    zero_deg_kernel<<<node_blocks, 256>>>();
    hist_kernel<<<edge_blocks, 256>>>();
    scan_kernel<<<1, SCAN_T>>>();
    zero_deg_kernel<<<node_blocks, 256>>>();
    scatter_kernel<<<edge_blocks, 256>>>();

    dim3 ggrid(HC / 128, (NNODES + 127) / 128);  // (4, 391)

    // ---- layer 1 (K=18, Kp=64) ----
    {
        size_t na = (size_t)NNODES * KP_SMALL;
        split_a_small_kernel<<<(int)((na + 255) / 256), 256>>>(x, F_IN, KP_SMALL);
        split_b_kernel<<<(HC * KP_SMALL + 255) / 256, 256>>>(W1, F_IN, KP_SMALL);
        cudaMemsetAsync(p_as, 0, alpha_bytes);
        cudaMemsetAsync(p_ad, 0, alpha_bytes);
        mma_gemm_kernel<<<ggrid, 256, GSMEM>>>(p_abf, p_bt, p_h, NNODES, KP_SMALL,
                                               a1_src, a1_dst, p_as, p_ad);
    }
    gat_aggr_kernel<<<NNODES, 256>>>(b1, 1);   // writes bf16 A' for layer 2

    // ---- layer 2 (K=512, Kp=1536) ----
    split_b_kernel<<<(HC * KP_BIG + 255) / 256, 256>>>(W2, HC, KP_BIG);
    cudaMemsetAsync(p_as, 0, alpha_bytes);
    cudaMemsetAsync(p_ad, 0, alpha_bytes);
    mma_gemm_kernel<<<ggrid, 256, GSMEM>>>(p_abf, p_bt, p_h, NNODES, KP_BIG,
                                           a2_src, a2_dst, p_as, p_ad);
    gat_aggr_kernel<<<NNODES, 256>>>(b2, 1);   // writes bf16 A' for layer 3

    // ---- layer 3 (K=512, Kp=1536) ----
    split_b_kernel<<<(HC * KP_BIG + 255) / 256, 256>>>(W3, HC, KP_BIG);
    cudaMemsetAsync(p_as, 0, alpha_bytes);
    cudaMemsetAsync(p_ad, 0, alpha_bytes);
    mma_gemm_kernel<<<ggrid, 256, GSMEM>>>(p_abf, p_bt, p_h, NNODES, KP_BIG,
                                           a3_src, a3_dst, p_as, p_ad);
    gat_aggr_kernel<<<NNODES, 256>>>(b3, 0);   // raw float to g_out

    final_kernel<<<NNODES, HID>>>(b3, W_out, b_out, y);
}